// round 14
// baseline (speedup 1.0000x reference)
#include <cuda_runtime.h>
#include <cuda_fp16.h>
#include <math.h>

#define BQ 8
#define SEQ 1024
#define DIMV 512
#define HEADS 8
#define DHEAD 64
#define NHEADS 64        // BQ*HEADS
#define QKVW 1536        // 3*HEADS*DHEAD

#define MU_C (1.0f/1024.0f)
#define NU_C (1.0f/1024.0f)

typedef unsigned int u32;

__device__ __forceinline__ u32 sptr(const void* p) {
    return (u32)__cvta_generic_to_shared(p);
}
__device__ __forceinline__ void ldsm_x4(u32& r0, u32& r1, u32& r2, u32& r3, u32 a) {
    asm volatile("ldmatrix.sync.aligned.m8n8.x4.shared.b16 {%0,%1,%2,%3},[%4];"
        : "=r"(r0), "=r"(r1), "=r"(r2), "=r"(r3) : "r"(a));
}
__device__ __forceinline__ void ldsm_x4t(u32& r0, u32& r1, u32& r2, u32& r3, u32 a) {
    asm volatile("ldmatrix.sync.aligned.m8n8.x4.trans.shared.b16 {%0,%1,%2,%3},[%4];"
        : "=r"(r0), "=r"(r1), "=r"(r2), "=r"(r3) : "r"(a));
}
__device__ __forceinline__ void mma_f16(float4& d, const u32* a, u32 b0, u32 b1) {
    asm volatile(
        "mma.sync.aligned.m16n8k16.row.col.f32.f16.f16.f32 "
        "{%0,%1,%2,%3},{%4,%5,%6,%7},{%8,%9},{%0,%1,%2,%3};"
        : "+f"(d.x), "+f"(d.y), "+f"(d.z), "+f"(d.w)
        : "r"(a[0]), "r"(a[1]), "r"(a[2]), "r"(a[3]), "r"(b0), "r"(b1));
}

// ---------------- scratch (device globals; no allocations allowed) ----------
__device__ __half g_qkv[(size_t)BQ * SEQ * QKVW];      // fp16 qkv
__device__ __half g_Eh[(size_t)NHEADS * SEQ * SEQ];    // E = exp(-C), fp16
__device__ float g_r[NHEADS * SEQ];
__device__ float g_rowsum[NHEADS * SEQ];
__device__ float g_cs1[NHEADS * SEQ];
__device__ float g_cs2[NHEADS * SEQ];
__device__ float g_cs3[NHEADS * SEQ];
__device__ __half g_ho[(size_t)BQ * SEQ * DIMV];       // fp16 head-merged out

// ---- qkv GEMM: fp32 A,B -> fp16 C. 128x128, BK=32, double-buffered ---------
__global__ __launch_bounds__(256) void qkv_gemm(
    const float* __restrict__ A, const float* __restrict__ Bm,
    __half* __restrict__ C, int M, int N, int K)
{
    __shared__ __half Ah[2][128 * 40];
    __shared__ __half Bh[2][32 * 136];
    const int t = threadIdx.x;
    const int m0 = blockIdx.y * 128, n0 = blockIdx.x * 128;
    const int lane = t & 31, w = t >> 5;
    const int wm = w & 3, wn = w >> 2;
    const int g = lane >> 2, tc = lane & 3;
    const int m0w = wm * 32, n0w = wn * 64;

    float4 acc[2][8];
#pragma unroll
    for (int mf = 0; mf < 2; mf++)
#pragma unroll
        for (int nf = 0; nf < 8; nf++) acc[mf][nf] = make_float4(0.f, 0.f, 0.f, 0.f);

    float4 avr[4], bvr[4];
#pragma unroll
    for (int q = 0; q < 4; q++) {
        int f = t + 256 * q;
        avr[q] = *(const float4*)(A + (size_t)(m0 + (f >> 3)) * K + (f & 7) * 4);
        bvr[q] = *(const float4*)(Bm + (size_t)(f >> 5) * N + n0 + (f & 31) * 4);
    }
#pragma unroll
    for (int q = 0; q < 4; q++) {
        int f = t + 256 * q;
        int row = f >> 3, c4 = (f & 7) * 4;
        *(__half2*)(Ah[0] + row * 40 + c4)     = __floats2half2_rn(avr[q].x, avr[q].y);
        *(__half2*)(Ah[0] + row * 40 + c4 + 2) = __floats2half2_rn(avr[q].z, avr[q].w);
        int kr = f >> 5, nc = (f & 31) * 4;
        *(__half2*)(Bh[0] + kr * 136 + nc)     = __floats2half2_rn(bvr[q].x, bvr[q].y);
        *(__half2*)(Bh[0] + kr * 136 + nc + 2) = __floats2half2_rn(bvr[q].z, bvr[q].w);
    }
    __syncthreads();

    const u32 aAddr0 = sptr(Ah[0]) + ((lane & 15) * 40 + ((lane >> 4) << 3)) * 2;
    const u32 bAddr0 = sptr(Bh[0]) +
        ((((lane >> 3) & 1) * 8 + (lane & 7)) * 136 + ((lane >> 4) << 3)) * 2;
    const u32 bufStepA = 128 * 40 * 2, bufStepB = 32 * 136 * 2;

    const int NT = K / 32;
    for (int kt = 0; kt < NT; kt++) {
        const int buf = kt & 1;
        if (kt + 1 < NT) {
            int ko = (kt + 1) * 32;
#pragma unroll
            for (int q = 0; q < 4; q++) {
                int f = t + 256 * q;
                avr[q] = *(const float4*)(A + (size_t)(m0 + (f >> 3)) * K + ko + (f & 7) * 4);
                bvr[q] = *(const float4*)(Bm + (size_t)(ko + (f >> 5)) * N + n0 + (f & 31) * 4);
            }
        }
        const u32 aB = aAddr0 + buf * bufStepA;
        const u32 bB = bAddr0 + buf * bufStepB;
#pragma unroll
        for (int ks = 0; ks < 32; ks += 16) {
            u32 a[2][4];
#pragma unroll
            for (int mf = 0; mf < 2; mf++)
                ldsm_x4(a[mf][0], a[mf][1], a[mf][2], a[mf][3],
                        aB + ((m0w + mf * 16) * 40 + ks) * 2);
#pragma unroll
            for (int nb = 0; nb < 4; nb++) {
                u32 b0, b1, b2, b3;
                ldsm_x4t(b0, b1, b2, b3, bB + (ks * 136 + n0w + nb * 16) * 2);
                mma_f16(acc[0][nb * 2 + 0], a[0], b0, b1);
                mma_f16(acc[0][nb * 2 + 1], a[0], b2, b3);
                mma_f16(acc[1][nb * 2 + 0], a[1], b0, b1);
                mma_f16(acc[1][nb * 2 + 1], a[1], b2, b3);
            }
        }
        if (kt + 1 < NT) {
            const int nb_ = buf ^ 1;
#pragma unroll
            for (int q = 0; q < 4; q++) {
                int f = t + 256 * q;
                int row = f >> 3, c4 = (f & 7) * 4;
                *(__half2*)(Ah[nb_] + row * 40 + c4)     = __floats2half2_rn(avr[q].x, avr[q].y);
                *(__half2*)(Ah[nb_] + row * 40 + c4 + 2) = __floats2half2_rn(avr[q].z, avr[q].w);
                int kr = f >> 5, nc = (f & 31) * 4;
                *(__half2*)(Bh[nb_] + kr * 136 + nc)     = __floats2half2_rn(bvr[q].x, bvr[q].y);
                *(__half2*)(Bh[nb_] + kr * 136 + nc + 2) = __floats2half2_rn(bvr[q].z, bvr[q].w);
            }
        }
        __syncthreads();
    }
#pragma unroll
    for (int mf = 0; mf < 2; mf++) {
        int gr = m0 + m0w + mf * 16 + g;
#pragma unroll
        for (int nf = 0; nf < 8; nf++) {
            int gc = n0 + n0w + nf * 8 + tc * 2;
            *(__half2*)(C + (size_t)gr * N + gc) =
                __floats2half2_rn(acc[mf][nf].x, acc[mf][nf].y);
            *(__half2*)(C + (size_t)(gr + 8) * N + gc) =
                __floats2half2_rn(acc[mf][nf].z, acc[mf][nf].w);
        }
    }
}

// ---- out GEMM: fp16 A, fp32 B -> fp32 C + bias; double-buffered ------------
__global__ __launch_bounds__(256) void out_gemm(
    const __half* __restrict__ A, const float* __restrict__ Bm,
    float* __restrict__ C, int M, int N, int K, const float* __restrict__ bias)
{
    __shared__ __half Ah[2][128 * 40];
    __shared__ __half Bh[2][32 * 136];
    const int t = threadIdx.x;
    const int m0 = blockIdx.y * 128, n0 = blockIdx.x * 128;
    const int lane = t & 31, w = t >> 5;
    const int wm = w & 3, wn = w >> 2;
    const int g = lane >> 2, tc = lane & 3;
    const int m0w = wm * 32, n0w = wn * 64;

    float4 acc[2][8];
#pragma unroll
    for (int mf = 0; mf < 2; mf++)
#pragma unroll
        for (int nf = 0; nf < 8; nf++) acc[mf][nf] = make_float4(0.f, 0.f, 0.f, 0.f);

    uint4 avr[2];
    float4 bvr[4];
#pragma unroll
    for (int q = 0; q < 2; q++) {
        int f = t + 256 * q;
        avr[q] = *(const uint4*)(A + (size_t)(m0 + (f >> 2)) * K + (f & 3) * 8);
    }
#pragma unroll
    for (int q = 0; q < 4; q++) {
        int f = t + 256 * q;
        bvr[q] = *(const float4*)(Bm + (size_t)(f >> 5) * N + n0 + (f & 31) * 4);
    }
#pragma unroll
    for (int q = 0; q < 2; q++) {
        int f = t + 256 * q;
        *(uint4*)(Ah[0] + (f >> 2) * 40 + (f & 3) * 8) = avr[q];
    }
#pragma unroll
    for (int q = 0; q < 4; q++) {
        int f = t + 256 * q;
        int kr = f >> 5, nc = (f & 31) * 4;
        *(__half2*)(Bh[0] + kr * 136 + nc)     = __floats2half2_rn(bvr[q].x, bvr[q].y);
        *(__half2*)(Bh[0] + kr * 136 + nc + 2) = __floats2half2_rn(bvr[q].z, bvr[q].w);
    }
    __syncthreads();

    const u32 aAddr0 = sptr(Ah[0]) + ((lane & 15) * 40 + ((lane >> 4) << 3)) * 2;
    const u32 bAddr0 = sptr(Bh[0]) +
        ((((lane >> 3) & 1) * 8 + (lane & 7)) * 136 + ((lane >> 4) << 3)) * 2;
    const u32 bufStepA = 128 * 40 * 2, bufStepB = 32 * 136 * 2;

    const int NT = K / 32;
    for (int kt = 0; kt < NT; kt++) {
        const int buf = kt & 1;
        if (kt + 1 < NT) {
            int ko = (kt + 1) * 32;
#pragma unroll
            for (int q = 0; q < 2; q++) {
                int f = t + 256 * q;
                avr[q] = *(const uint4*)(A + (size_t)(m0 + (f >> 2)) * K + ko + (f & 3) * 8);
            }
#pragma unroll
            for (int q = 0; q < 4; q++) {
                int f = t + 256 * q;
                bvr[q] = *(const float4*)(Bm + (size_t)(ko + (f >> 5)) * N + n0 + (f & 31) * 4);
            }
        }
        const u32 aB = aAddr0 + buf * bufStepA;
        const u32 bB = bAddr0 + buf * bufStepB;
#pragma unroll
        for (int ks = 0; ks < 32; ks += 16) {
            u32 a[2][4];
#pragma unroll
            for (int mf = 0; mf < 2; mf++)
                ldsm_x4(a[mf][0], a[mf][1], a[mf][2], a[mf][3],
                        aB + ((m0w + mf * 16) * 40 + ks) * 2);
#pragma unroll
            for (int nb = 0; nb < 4; nb++) {
                u32 b0, b1, b2, b3;
                ldsm_x4t(b0, b1, b2, b3, bB + (ks * 136 + n0w + nb * 16) * 2);
                mma_f16(acc[0][nb * 2 + 0], a[0], b0, b1);
                mma_f16(acc[0][nb * 2 + 1], a[0], b2, b3);
                mma_f16(acc[1][nb * 2 + 0], a[1], b0, b1);
                mma_f16(acc[1][nb * 2 + 1], a[1], b2, b3);
            }
        }
        if (kt + 1 < NT) {
            const int nb_ = buf ^ 1;
#pragma unroll
            for (int q = 0; q < 2; q++) {
                int f = t + 256 * q;
                *(uint4*)(Ah[nb_] + (f >> 2) * 40 + (f & 3) * 8) = avr[q];
            }
#pragma unroll
            for (int q = 0; q < 4; q++) {
                int f = t + 256 * q;
                int kr = f >> 5, nc = (f & 31) * 4;
                *(__half2*)(Bh[nb_] + kr * 136 + nc)     = __floats2half2_rn(bvr[q].x, bvr[q].y);
                *(__half2*)(Bh[nb_] + kr * 136 + nc + 2) = __floats2half2_rn(bvr[q].z, bvr[q].w);
            }
        }
        __syncthreads();
    }
#pragma unroll
    for (int mf = 0; mf < 2; mf++) {
        int gr = m0 + m0w + mf * 16 + g;
#pragma unroll
        for (int nf = 0; nf < 8; nf++) {
            int gc = n0 + n0w + nf * 8 + tc * 2;
            float2 lo = make_float2(acc[mf][nf].x + bias[gc],
                                    acc[mf][nf].y + bias[gc + 1]);
            float2 hi = make_float2(acc[mf][nf].z + bias[gc],
                                    acc[mf][nf].w + bias[gc + 1]);
            *(float2*)(C + (size_t)gr * N + gc) = lo;
            *(float2*)(C + (size_t)(gr + 8) * N + gc) = hi;
        }
    }
}

// ------- dots (fp16 mma): E = exp(-scale*q k^T) fp16, fused row-sum ---------
__global__ __launch_bounds__(256) void qk_dots_exp(
    const __half* __restrict__ qkv, __half* __restrict__ Eh,
    float* __restrict__ rowsum)
{
    __shared__ __half Ah[128 * 72];   // [i][d]
    __shared__ __half Bh[128 * 72];   // [j][d]
    const int bh = blockIdx.z, b = bh >> 3, h = bh & 7;
    const int i0 = blockIdx.y * 128, j0 = blockIdx.x * 128;
    const __half* qbase = qkv + (size_t)b * SEQ * QKVW + h * DHEAD;
    const __half* kbase = qkv + (size_t)b * SEQ * QKVW + 512 + h * DHEAD;

    const int t = threadIdx.x;
    const int lane = t & 31, w = t >> 5;
    const int wm = w & 3, wn = w >> 2;
    const int g = lane >> 2, tc = lane & 3;
    const int m0w = wm * 32, n0w = wn * 64;

    float4 acc[2][8];
#pragma unroll
    for (int mf = 0; mf < 2; mf++)
#pragma unroll
        for (int nf = 0; nf < 8; nf++) acc[mf][nf] = make_float4(0.f, 0.f, 0.f, 0.f);

#pragma unroll
    for (int q = 0; q < 4; q++) {
        int f = t + 256 * q;
        int row = f >> 3, c8 = (f & 7) * 8;
        *(uint4*)(Ah + row * 72 + c8) =
            *(const uint4*)(qbase + (size_t)(i0 + row) * QKVW + c8);
        *(uint4*)(Bh + row * 72 + c8) =
            *(const uint4*)(kbase + (size_t)(j0 + row) * QKVW + c8);
    }
    __syncthreads();

    const u32 aAddrBase = sptr(Ah) + ((lane & 15) * 72 + ((lane >> 4) << 3)) * 2;
    const u32 bAddrBase = sptr(Bh) +
        ((((lane >> 4) << 3) + (lane & 7)) * 72 + (((lane >> 3) & 1) * 8)) * 2;

#pragma unroll
    for (int ks = 0; ks < 64; ks += 16) {
        u32 a[2][4];
#pragma unroll
        for (int mf = 0; mf < 2; mf++)
            ldsm_x4(a[mf][0], a[mf][1], a[mf][2], a[mf][3],
                    aAddrBase + ((m0w + mf * 16) * 72 + ks) * 2);
#pragma unroll
        for (int nb = 0; nb < 4; nb++) {
            u32 b0, b1, b2, b3;
            ldsm_x4(b0, b1, b2, b3,
                    bAddrBase + ((n0w + nb * 16) * 72 + ks) * 2);
            mma_f16(acc[0][nb * 2 + 0], a[0], b0, b1);
            mma_f16(acc[0][nb * 2 + 1], a[0], b2, b3);
            mma_f16(acc[1][nb * 2 + 0], a[1], b0, b1);
            mma_f16(acc[1][nb * 2 + 1], a[1], b2, b3);
        }
    }

    __half* Ehp = Eh + (size_t)bh * SEQ * SEQ;
#pragma unroll
    for (int mf = 0; mf < 2; mf++) {
        int gi = i0 + m0w + mf * 16 + g;
        float rs0 = 0.f, rs1 = 0.f;
#pragma unroll
        for (int nf = 0; nf < 8; nf++) {
            int gj = j0 + n0w + nf * 8 + tc * 2;
            float e0 = __expf(-0.125f * acc[mf][nf].x);
            float e1 = __expf(-0.125f * acc[mf][nf].y);
            float e2 = __expf(-0.125f * acc[mf][nf].z);
            float e3 = __expf(-0.125f * acc[mf][nf].w);
            *(__half2*)(Ehp + (size_t)gi * SEQ + gj) = __floats2half2_rn(e0, e1);
            *(__half2*)(Ehp + (size_t)(gi + 8) * SEQ + gj) = __floats2half2_rn(e2, e3);
            rs0 += e0 + e1; rs1 += e2 + e3;
        }
        rs0 += __shfl_xor_sync(0xffffffffu, rs0, 1);
        rs0 += __shfl_xor_sync(0xffffffffu, rs0, 2);
        rs1 += __shfl_xor_sync(0xffffffffu, rs1, 1);
        rs1 += __shfl_xor_sync(0xffffffffu, rs1, 2);
        if (tc == 0) {
            atomicAdd(&rowsum[bh * SEQ + gi], rs0);
            atomicAdd(&rowsum[bh * SEQ + gi + 8], rs1);
        }
    }
}

// ---- col pass over fp16 E ---------------------------------------------------
__global__ __launch_bounds__(256) void colpass_h(
    const __half* __restrict__ Eh, const float* __restrict__ rvec,
    float* __restrict__ colsum, int recip)
{
    const int bh = blockIdx.y;
    const int i0 = blockIdx.x * 64;
    const int t = threadIdx.x;
    __shared__ float rs[64];
    if (t < 64) {
        float rv = rvec[bh * SEQ + i0 + t];
        rs[t] = recip ? (MU_C / rv) : rv;
    }
    __syncthreads();

    const __half* Ep = Eh + (size_t)bh * SEQ * SEQ + (size_t)i0 * SEQ;
    const int j = t * 4;
    float ax = 0.f, ay = 0.f, az = 0.f, aw = 0.f;
#pragma unroll 8
    for (int i = 0; i < 64; i++) {
        uint2 raw = *(const uint2*)(Ep + (size_t)i * SEQ + j);
        float2 f0 = __half22float2(*(__half2*)&raw.x);
        float2 f1 = __half22float2(*(__half2*)&raw.y);
        float rv = rs[i];
        ax = fmaf(f0.x, rv, ax); ay = fmaf(f0.y, rv, ay);
        az = fmaf(f1.x, rv, az); aw = fmaf(f1.y, rv, aw);
    }
    atomicAdd(&colsum[bh * SEQ + j + 0], ax);
    atomicAdd(&colsum[bh * SEQ + j + 1], ay);
    atomicAdd(&colsum[bh * SEQ + j + 2], az);
    atomicAdd(&colsum[bh * SEQ + j + 3], aw);
}

// ---- fused row+col pass ------------------------------------------------------
__global__ __launch_bounds__(256) void rc_fused_h(
    const __half* __restrict__ Eh, const float* __restrict__ cs_in,
    float* __restrict__ cs_out, float* __restrict__ rvec)
{
    __shared__ float cs[SEQ];
    __shared__ float rl[32];
    const int bh = blockIdx.y, i0 = blockIdx.x * 32;
    const int t = threadIdx.x, lane = t & 31, w = t >> 5;

#pragma unroll
    for (int q = 0; q < 4; q++) {
        int j = t + 256 * q;
        cs[j] = NU_C / cs_in[bh * SEQ + j];
    }
    __syncthreads();

    const __half* Ep = Eh + (size_t)bh * SEQ * SEQ + (size_t)i0 * SEQ;

#pragma unroll
    for (int rr = 0; rr < 4; rr++) {
        const int row = w * 4 + rr;
        const __half* Er = Ep + (size_t)row * SEQ;
        float acc = 0.f;
#pragma unroll
        for (int it = 0; it < 4; it++) {
            int j = it * 256 + lane * 8;
            uint4 raw = *(const uint4*)(Er + j);
            const __half2* hp = (const __half2*)&raw;
#pragma unroll
            for (int p = 0; p < 4; p++) {
                float2 f = __half22float2(hp[p]);
                acc += f.x * cs[j + p * 2] + f.y * cs[j + p * 2 + 1];
            }
        }
#pragma unroll
        for (int o = 16; o > 0; o >>= 1)
            acc += __shfl_xor_sync(0xffffffffu, acc, o);
        if (lane == 0) {
            float rv = MU_C / acc;
            rl[row] = rv;
            rvec[bh * SEQ + i0 + row] = rv;
        }
    }
    __syncthreads();

    const int j = t * 4;
    float ax = 0.f, ay = 0.f, az = 0.f, aw = 0.f;
#pragma unroll 8
    for (int i = 0; i < 32; i++) {
        uint2 raw = *(const uint2*)(Ep + (size_t)i * SEQ + j);
        float2 f0 = __half22float2(*(__half2*)&raw.x);
        float2 f1 = __half22float2(*(__half2*)&raw.y);
        float rv = rl[i];
        ax = fmaf(f0.x, rv, ax); ay = fmaf(f0.y, rv, ay);
        az = fmaf(f1.x, rv, az); aw = fmaf(f1.y, rv, aw);
    }
    atomicAdd(&cs_out[bh * SEQ + j + 0], ax);
    atomicAdd(&cs_out[bh * SEQ + j + 1], ay);
    atomicAdd(&cs_out[bh * SEQ + j + 2], az);
    atomicAdd(&cs_out[bh * SEQ + j + 3], aw);
}

__global__ void init_sums(float* __restrict__ rowsum, float* __restrict__ c1,
                          float* __restrict__ c2, float* __restrict__ c3)
{
    int i = blockIdx.x * 256 + threadIdx.x;
    rowsum[i] = 0.f; c1[i] = 0.f; c2[i] = 0.f; c3[i] = 0.f;
}

// --- per-head AV (fp16 mma, BK=64, double-buffered dynamic smem) -------------
// dyn smem: Es[2][128*72], Vs[2][64*72] halves, then cr[1024], rn[128] floats
#define AV_EST (128 * 72)
#define AV_VST (64 * 72)
#define AV_HALVES (2 * AV_EST + 2 * AV_VST)
#define AV_SMEM_BYTES (AV_HALVES * 2 + (SEQ + 128) * 4)

__global__ __launch_bounds__(256) void av_gemm(
    const __half* __restrict__ Eh, const float* __restrict__ r,
    const float* __restrict__ colsum3, const __half* __restrict__ qkv,
    float* __restrict__ attn, __half* __restrict__ ho, int write_attn)
{
    extern __shared__ char dsm[];
    __half* Es = (__half*)dsm;                       // 2 bufs
    __half* Vs = Es + 2 * AV_EST;                    // 2 bufs
    float* cr = (float*)(dsm + AV_HALVES * 2);
    float* rn = cr + SEQ;

    const int bh = blockIdx.y, b = bh >> 3, h = bh & 7;
    const int i0 = blockIdx.x * 128;
    const int t = threadIdx.x;
    const int lane = t & 31, w = t >> 5;
    const int wm = w & 3, wn = w >> 2;
    const int g = lane >> 2, tc = lane & 3;
    const int m0w = wm * 32, n0w = wn * 32;

    if (t < 128) rn[t] = r[bh * SEQ + i0 + t] * 1024.0f;
#pragma unroll
    for (int q = 0; q < 4; q++) {
        int j = t + 256 * q;
        cr[j] = NU_C / colsum3[bh * SEQ + j];
    }
    __syncthreads();

    const __half* Ep = Eh + (size_t)bh * SEQ * SEQ;
    const __half* vb = qkv + (size_t)b * SEQ * QKVW + 1024 + h * DHEAD;
    float* ap = attn + (size_t)bh * SEQ * SEQ;

    float4 acc[2][4];
#pragma unroll
    for (int mf = 0; mf < 2; mf++)
#pragma unroll
        for (int nf = 0; nf < 4; nf++) acc[mf][nf] = make_float4(0.f, 0.f, 0.f, 0.f);

    const u32 aAddr0 = sptr(Es) + ((lane & 15) * 72 + ((lane >> 4) << 3)) * 2;
    const u32 bAddr0 = sptr(Vs) +
        ((((lane >> 3) & 1) * 8 + (lane & 7)) * 72 + ((lane >> 4) << 3)) * 2;
    const u32 stepE = AV_EST * 2, stepV = AV_VST * 2;

    uint4 er[4], vr[2];
    // prologue: tile 0 -> regs (+ attn write) -> buf 0
#pragma unroll
    for (int q = 0; q < 4; q++) {
        int f = t + 256 * q;
        int i = f >> 3, c8 = (f & 7) * 8;
        er[q] = *(const uint4*)(Ep + (size_t)(i0 + i) * SEQ + c8);
        if (write_attn) {
            float rv = rn[i];
            const __half2* hp = (const __half2*)&er[q];
            float* dst = ap + (size_t)(i0 + i) * SEQ + c8;
#pragma unroll
            for (int p = 0; p < 4; p++) {
                float2 e = __half22float2(hp[p]);
                float2 o;
                o.x = rv * e.x * cr[c8 + p * 2];
                o.y = rv * e.y * cr[c8 + p * 2 + 1];
                *(float2*)(dst + p * 2) = o;
            }
        }
    }
#pragma unroll
    for (int q = 0; q < 2; q++) {
        int f = t + 256 * q;
        vr[q] = *(const uint4*)(vb + (size_t)(f >> 3) * QKVW + (f & 7) * 8);
    }
#pragma unroll
    for (int q = 0; q < 4; q++) {
        int f = t + 256 * q;
        *(uint4*)(Es + (f >> 3) * 72 + (f & 7) * 8) = er[q];
    }
#pragma unroll
    for (int q = 0; q < 2; q++) {
        int f = t + 256 * q;
        int row = f >> 3, c8 = (f & 7) * 8;
        float cw = cr[row];
        const __half2* hp = (const __half2*)&vr[q];
        __half2* dst = (__half2*)(Vs + row * 72 + c8);
#pragma unroll
        for (int p = 0; p < 4; p++) {
            float2 v = __half22float2(hp[p]);
            dst[p] = __floats2half2_rn(v.x * cw, v.y * cw);
        }
    }
    __syncthreads();

    for (int jt = 0; jt < 16; jt++) {
        const int buf = jt & 1;
        const int j0n = (jt + 1) * 64;
        if (jt + 1 < 16) {
#pragma unroll
            for (int q = 0; q < 4; q++) {
                int f = t + 256 * q;
                int i = f >> 3, c8 = (f & 7) * 8;
                er[q] = *(const uint4*)(Ep + (size_t)(i0 + i) * SEQ + j0n + c8);
                if (write_attn) {
                    float rv = rn[i];
                    const __half2* hp = (const __half2*)&er[q];
                    float* dst = ap + (size_t)(i0 + i) * SEQ + j0n + c8;
#pragma unroll
                    for (int p = 0; p < 4; p++) {
                        float2 e = __half22float2(hp[p]);
                        float2 o;
                        o.x = rv * e.x * cr[j0n + c8 + p * 2];
                        o.y = rv * e.y * cr[j0n + c8 + p * 2 + 1];
                        *(float2*)(dst + p * 2) = o;
                    }
                }
            }
#pragma unroll
            for (int q = 0; q < 2; q++) {
                int f = t + 256 * q;
                vr[q] = *(const uint4*)(vb + (size_t)(j0n + (f >> 3)) * QKVW + (f & 7) * 8);
            }
        }
        const u32 aB = aAddr0 + buf * stepE;
        const u32 bB = bAddr0 + buf * stepV;
#pragma unroll
        for (int ks = 0; ks < 64; ks += 16) {
            u32 a[2][4];
#pragma unroll
            for (int mf = 0; mf < 2; mf++)
                ldsm_x4(a[mf][0], a[mf][1], a[mf][2], a[mf][3],
                        aB + ((m0w + mf * 16) * 72 + ks) * 2);
#pragma unroll
            for (int nb = 0; nb < 2; nb++) {
                u32 b0, b1, b2, b3;
                ldsm_x4t(b0, b1, b2, b3, bB + (ks * 72 + n0w + nb * 16) * 2);
                mma_f16(acc[0][nb * 2 + 0], a[0], b0, b1);
                mma_f16(acc[0][nb * 2 + 1], a[0], b2, b3);
                mma_f16(acc[1][nb * 2 + 0], a[1], b0, b1);
                mma_f16(acc[1][nb * 2 + 1], a[1], b2, b3);
            }
        }
        if (jt + 1 < 16) {
            const int nb_ = buf ^ 1;
            __half* Ew = Es + nb_ * AV_EST;
            __half* Vw = Vs + nb_ * AV_VST;
#pragma unroll
            for (int q = 0; q < 4; q++) {
                int f = t + 256 * q;
                *(uint4*)(Ew + (f >> 3) * 72 + (f & 7) * 8) = er[q];
            }
#pragma unroll
            for (int q = 0; q < 2; q++) {
                int f = t + 256 * q;
                int row = f >> 3, c8 = (f & 7) * 8;
                float cw = cr[j0n + row];
                const __half2* hp = (const __half2*)&vr[q];
                __half2* dst = (__half2*)(Vw + row * 72 + c8);
#pragma unroll
                for (int p = 0; p < 4; p++) {
                    float2 v = __half22float2(hp[p]);
                    dst[p] = __floats2half2_rn(v.x * cw, v.y * cw);
                }
            }
        }
        __syncthreads();
    }
#pragma unroll
    for (int mf = 0; mf < 2; mf++) {
        int il = m0w + mf * 16 + g;
        float rv0 = rn[il], rv1 = rn[il + 8];
        __half* hp0 = ho + (size_t)(b * SEQ + i0 + il) * DIMV + h * DHEAD;
        __half* hp1 = ho + (size_t)(b * SEQ + i0 + il + 8) * DIMV + h * DHEAD;
#pragma unroll
        for (int nf = 0; nf < 4; nf++) {
            int gc = n0w + nf * 8 + tc * 2;
            *(__half2*)(hp0 + gc) =
                __floats2half2_rn(acc[mf][nf].x * rv0, acc[mf][nf].y * rv0);
            *(__half2*)(hp1 + gc) =
                __floats2half2_rn(acc[mf][nf].z * rv1, acc[mf][nf].w * rv1);
        }
    }
}

// ---------------- launcher ---------------------------------------------------
extern "C" void kernel_launch(void* const* d_in, const int* in_sizes, int n_in,
                              void* d_out, int out_size)
{
    const float* x    = (const float*)d_in[0];
    const float* Wqkv = (const float*)d_in[1];
    const float* Wout = (const float*)d_in[2];
    const float* bout = (const float*)d_in[3];
    float* out = (float*)d_out;

    float *rp, *rsp, *c1p, *c2p, *c3p;
    __half *qkvp, *Ehp, *hop;
    cudaGetSymbolAddress((void**)&qkvp, g_qkv);
    cudaGetSymbolAddress((void**)&Ehp,  g_Eh);
    cudaGetSymbolAddress((void**)&rp,   g_r);
    cudaGetSymbolAddress((void**)&rsp,  g_rowsum);
    cudaGetSymbolAddress((void**)&c1p,  g_cs1);
    cudaGetSymbolAddress((void**)&c2p,  g_cs2);
    cudaGetSymbolAddress((void**)&c3p,  g_cs3);
    cudaGetSymbolAddress((void**)&hop,  g_ho);

    const size_t FIN = (size_t)BQ * SEQ * DIMV;
    const size_t ATT = (size_t)NHEADS * SEQ * SEQ;
    float* fin_ptr = 0;
    float* attn_ptr = 0;
    if ((size_t)out_size >= FIN + ATT) { fin_ptr = out; attn_ptr = out + FIN; }
    else if ((size_t)out_size == ATT)  { attn_ptr = out; }
    else                               { fin_ptr = out; }

    const int NV = NHEADS * SEQ;
    cudaFuncSetAttribute(av_gemm, cudaFuncAttributeMaxDynamicSharedMemorySize,
                         AV_SMEM_BYTES);

    init_sums<<<NV / 256, 256>>>(rsp, c1p, c2p, c3p);

    // 1) qkv = x @ W_qkv  (fp16 mma, double-buffered)
    qkv_gemm<<<dim3(QKVW / 128, (BQ * SEQ) / 128), 256>>>(
        x, Wqkv, qkvp, BQ * SEQ, QKVW, DIMV);

    // 2) E = exp(-scale*q k^T) fp16, fused rowsum (c0 = 1)
    qk_dots_exp<<<dim3(SEQ / 128, SEQ / 128, NHEADS), 256>>>(qkvp, Ehp, rsp);

    // 3) Sinkhorn: col1, then two fused (row+col) passes
    colpass_h<<<dim3(SEQ / 64, NHEADS), 256>>>(Ehp, rsp, c1p, 1);
    rc_fused_h<<<dim3(SEQ / 32, NHEADS), 256>>>(Ehp, c1p, c2p, rp);   // r2, cs2
    rc_fused_h<<<dim3(SEQ / 32, NHEADS), 256>>>(Ehp, c2p, c3p, rp);   // r3, cs3

    // 4) attn = r*E*c*n (fused fp32 write) and ho = attn @ V (pipelined)
    av_gemm<<<dim3(SEQ / 128, NHEADS), 256, AV_SMEM_BYTES>>>(
        Ehp, rp, c3p, qkvp, attn_ptr ? attn_ptr : (float*)out, hop,
        attn_ptr ? 1 : 0);

    // 5) final = ho @ W_out + b_out  (fp16 mma, double-buffered)
    if (fin_ptr)
        out_gemm<<<dim3(DIMV / 128, (BQ * SEQ) / 128), 256>>>(
            hop, Wout, fin_ptr, BQ * SEQ, DIMV, DIMV, bout);
}

// round 15
// speedup vs baseline: 1.0152x; 1.0152x over previous
#include <cuda_runtime.h>
#include <cuda_fp16.h>
#include <math.h>

#define BQ 8
#define SEQ 1024
#define DIMV 512
#define HEADS 8
#define DHEAD 64
#define NHEADS 64        // BQ*HEADS
#define QKVW 1536        // 3*HEADS*DHEAD

#define MU_C (1.0f/1024.0f)
#define NU_C (1.0f/1024.0f)

#define XN   ((size_t)BQ * SEQ * DIMV)     // 4,194,304
#define WQN  ((size_t)DIMV * QKVW)         //   786,432
#define WON  ((size_t)DIMV * DIMV)         //   262,144

typedef unsigned int u32;

__device__ __forceinline__ u32 sptr(const void* p) {
    return (u32)__cvta_generic_to_shared(p);
}
__device__ __forceinline__ void ldsm_x4(u32& r0, u32& r1, u32& r2, u32& r3, u32 a) {
    asm volatile("ldmatrix.sync.aligned.m8n8.x4.shared.b16 {%0,%1,%2,%3},[%4];"
        : "=r"(r0), "=r"(r1), "=r"(r2), "=r"(r3) : "r"(a));
}
__device__ __forceinline__ void ldsm_x4t(u32& r0, u32& r1, u32& r2, u32& r3, u32 a) {
    asm volatile("ldmatrix.sync.aligned.m8n8.x4.trans.shared.b16 {%0,%1,%2,%3},[%4];"
        : "=r"(r0), "=r"(r1), "=r"(r2), "=r"(r3) : "r"(a));
}
__device__ __forceinline__ void mma_f16(float4& d, const u32* a, u32 b0, u32 b1) {
    asm volatile(
        "mma.sync.aligned.m16n8k16.row.col.f32.f16.f16.f32 "
        "{%0,%1,%2,%3},{%4,%5,%6,%7},{%8,%9},{%0,%1,%2,%3};"
        : "+f"(d.x), "+f"(d.y), "+f"(d.z), "+f"(d.w)
        : "r"(a[0]), "r"(a[1]), "r"(a[2]), "r"(a[3]), "r"(b0), "r"(b1));
}

// ---------------- scratch (device globals; no allocations allowed) ----------
__device__ __half g_xh[XN];                           // fp16 x
__device__ __half g_wqh[WQN];                         // fp16 W_qkv
__device__ __half g_woh[WON];                         // fp16 W_out
__device__ __half g_qkv[(size_t)BQ * SEQ * QKVW];     // fp16 qkv
__device__ __half g_Eh[(size_t)NHEADS * SEQ * SEQ];   // E = exp(-C), fp16
__device__ float g_r[NHEADS * SEQ];
__device__ float g_rowsum[NHEADS * SEQ];
__device__ float g_cs1[NHEADS * SEQ];
__device__ float g_cs2[NHEADS * SEQ];
__device__ float g_cs3[NHEADS * SEQ];
__device__ __half g_ho[(size_t)BQ * SEQ * DIMV];      // fp16 head-merged out

// ---- convert x, W_qkv, W_out to fp16; zero the Sinkhorn accumulators -------
__global__ __launch_bounds__(256) void prep(
    const float* __restrict__ x, const float* __restrict__ Wq,
    const float* __restrict__ Wo,
    __half* __restrict__ xh, __half* __restrict__ wqh, __half* __restrict__ woh,
    float* __restrict__ rowsum, float* __restrict__ c1,
    float* __restrict__ c2, float* __restrict__ c3)
{
    const size_t tid = (size_t)blockIdx.x * 256 + threadIdx.x;
    const size_t stride = (size_t)gridDim.x * 256;
    const size_t TOT = (XN + WQN + WON) / 4;
    for (size_t f = tid; f < TOT; f += stride) {
        size_t e = f * 4;
        const float* src; __half* dst; size_t off;
        if (e < XN)            { src = x;  dst = xh;  off = e; }
        else if (e < XN + WQN) { src = Wq; dst = wqh; off = e - XN; }
        else                   { src = Wo; dst = woh; off = e - XN - WQN; }
        float4 v = *(const float4*)(src + off);
        *(__half2*)(dst + off)     = __floats2half2_rn(v.x, v.y);
        *(__half2*)(dst + off + 2) = __floats2half2_rn(v.z, v.w);
    }
    const size_t NV = (size_t)NHEADS * SEQ;
    for (size_t i = tid; i < NV; i += stride) {
        rowsum[i] = 0.f; c1[i] = 0.f; c2[i] = 0.f; c3[i] = 0.f;
    }
}

// ---- fp16 GEMM: A,B fp16 -> C (fp16 or fp32+bias). 128x128, BK=32, dbuf ----
template<int HALF_OUT>
__global__ __launch_bounds__(256) void gemm_hh(
    const __half* __restrict__ A, const __half* __restrict__ Bm,
    void* __restrict__ Cv, int M, int N, int K, const float* __restrict__ bias)
{
    __shared__ __half Ah[2][128 * 40];
    __shared__ __half Bh[2][32 * 136];
    const int t = threadIdx.x;
    const int m0 = blockIdx.y * 128, n0 = blockIdx.x * 128;
    const int lane = t & 31, w = t >> 5;
    const int wm = w & 3, wn = w >> 2;
    const int g = lane >> 2, tc = lane & 3;
    const int m0w = wm * 32, n0w = wn * 64;

    float4 acc[2][8];
#pragma unroll
    for (int mf = 0; mf < 2; mf++)
#pragma unroll
        for (int nf = 0; nf < 8; nf++) acc[mf][nf] = make_float4(0.f, 0.f, 0.f, 0.f);

    uint4 avr[2], bvr[2];
#pragma unroll
    for (int q = 0; q < 2; q++) {
        int f = t + 256 * q;
        avr[q] = *(const uint4*)(A + (size_t)(m0 + (f >> 2)) * K + (f & 3) * 8);
        bvr[q] = *(const uint4*)(Bm + (size_t)(f >> 4) * N + n0 + (f & 15) * 8);
    }
#pragma unroll
    for (int q = 0; q < 2; q++) {
        int f = t + 256 * q;
        *(uint4*)(Ah[0] + (f >> 2) * 40 + (f & 3) * 8) = avr[q];
        *(uint4*)(Bh[0] + (f >> 4) * 136 + (f & 15) * 8) = bvr[q];
    }
    __syncthreads();

    const u32 aAddr0 = sptr(Ah[0]) + ((lane & 15) * 40 + ((lane >> 4) << 3)) * 2;
    const u32 bAddr0 = sptr(Bh[0]) +
        ((((lane >> 3) & 1) * 8 + (lane & 7)) * 136 + ((lane >> 4) << 3)) * 2;
    const u32 bufStepA = 128 * 40 * 2, bufStepB = 32 * 136 * 2;

    const int NT = K / 32;
    for (int kt = 0; kt < NT; kt++) {
        const int buf = kt & 1;
        if (kt + 1 < NT) {
            int ko = (kt + 1) * 32;
#pragma unroll
            for (int q = 0; q < 2; q++) {
                int f = t + 256 * q;
                avr[q] = *(const uint4*)(A + (size_t)(m0 + (f >> 2)) * K + ko + (f & 3) * 8);
                bvr[q] = *(const uint4*)(Bm + (size_t)(ko + (f >> 4)) * N + n0 + (f & 15) * 8);
            }
        }
        const u32 aB = aAddr0 + buf * bufStepA;
        const u32 bB = bAddr0 + buf * bufStepB;
#pragma unroll
        for (int ks = 0; ks < 32; ks += 16) {
            u32 a[2][4];
#pragma unroll
            for (int mf = 0; mf < 2; mf++)
                ldsm_x4(a[mf][0], a[mf][1], a[mf][2], a[mf][3],
                        aB + ((m0w + mf * 16) * 40 + ks) * 2);
#pragma unroll
            for (int nb = 0; nb < 4; nb++) {
                u32 b0, b1, b2, b3;
                ldsm_x4t(b0, b1, b2, b3, bB + (ks * 136 + n0w + nb * 16) * 2);
                mma_f16(acc[0][nb * 2 + 0], a[0], b0, b1);
                mma_f16(acc[0][nb * 2 + 1], a[0], b2, b3);
                mma_f16(acc[1][nb * 2 + 0], a[1], b0, b1);
                mma_f16(acc[1][nb * 2 + 1], a[1], b2, b3);
            }
        }
        if (kt + 1 < NT) {
            const int nb_ = buf ^ 1;
#pragma unroll
            for (int q = 0; q < 2; q++) {
                int f = t + 256 * q;
                *(uint4*)(Ah[nb_] + (f >> 2) * 40 + (f & 3) * 8) = avr[q];
                *(uint4*)(Bh[nb_] + (f >> 4) * 136 + (f & 15) * 8) = bvr[q];
            }
        }
        __syncthreads();
    }
#pragma unroll
    for (int mf = 0; mf < 2; mf++) {
        int gr = m0 + m0w + mf * 16 + g;
#pragma unroll
        for (int nf = 0; nf < 8; nf++) {
            int gc = n0 + n0w + nf * 8 + tc * 2;
            if (HALF_OUT) {
                __half* C = (__half*)Cv;
                *(__half2*)(C + (size_t)gr * N + gc) =
                    __floats2half2_rn(acc[mf][nf].x, acc[mf][nf].y);
                *(__half2*)(C + (size_t)(gr + 8) * N + gc) =
                    __floats2half2_rn(acc[mf][nf].z, acc[mf][nf].w);
            } else {
                float* C = (float*)Cv;
                float2 lo = make_float2(acc[mf][nf].x + bias[gc],
                                        acc[mf][nf].y + bias[gc + 1]);
                float2 hi = make_float2(acc[mf][nf].z + bias[gc],
                                        acc[mf][nf].w + bias[gc + 1]);
                *(float2*)(C + (size_t)gr * N + gc) = lo;
                *(float2*)(C + (size_t)(gr + 8) * N + gc) = hi;
            }
        }
    }
}

// ------- dots (fp16 mma): E = exp(-scale*q k^T) fp16, fused row-sum ---------
__global__ __launch_bounds__(256) void qk_dots_exp(
    const __half* __restrict__ qkv, __half* __restrict__ Eh,
    float* __restrict__ rowsum)
{
    __shared__ __half Ah[128 * 72];   // [i][d]
    __shared__ __half Bh[128 * 72];   // [j][d]
    const int bh = blockIdx.z, b = bh >> 3, h = bh & 7;
    const int i0 = blockIdx.y * 128, j0 = blockIdx.x * 128;
    const __half* qbase = qkv + (size_t)b * SEQ * QKVW + h * DHEAD;
    const __half* kbase = qkv + (size_t)b * SEQ * QKVW + 512 + h * DHEAD;

    const int t = threadIdx.x;
    const int lane = t & 31, w = t >> 5;
    const int wm = w & 3, wn = w >> 2;
    const int g = lane >> 2, tc = lane & 3;
    const int m0w = wm * 32, n0w = wn * 64;

    float4 acc[2][8];
#pragma unroll
    for (int mf = 0; mf < 2; mf++)
#pragma unroll
        for (int nf = 0; nf < 8; nf++) acc[mf][nf] = make_float4(0.f, 0.f, 0.f, 0.f);

#pragma unroll
    for (int q = 0; q < 4; q++) {
        int f = t + 256 * q;
        int row = f >> 3, c8 = (f & 7) * 8;
        *(uint4*)(Ah + row * 72 + c8) =
            *(const uint4*)(qbase + (size_t)(i0 + row) * QKVW + c8);
        *(uint4*)(Bh + row * 72 + c8) =
            *(const uint4*)(kbase + (size_t)(j0 + row) * QKVW + c8);
    }
    __syncthreads();

    const u32 aAddrBase = sptr(Ah) + ((lane & 15) * 72 + ((lane >> 4) << 3)) * 2;
    const u32 bAddrBase = sptr(Bh) +
        ((((lane >> 4) << 3) + (lane & 7)) * 72 + (((lane >> 3) & 1) * 8)) * 2;

#pragma unroll
    for (int ks = 0; ks < 64; ks += 16) {
        u32 a[2][4];
#pragma unroll
        for (int mf = 0; mf < 2; mf++)
            ldsm_x4(a[mf][0], a[mf][1], a[mf][2], a[mf][3],
                    aAddrBase + ((m0w + mf * 16) * 72 + ks) * 2);
#pragma unroll
        for (int nb = 0; nb < 4; nb++) {
            u32 b0, b1, b2, b3;
            ldsm_x4(b0, b1, b2, b3,
                    bAddrBase + ((n0w + nb * 16) * 72 + ks) * 2);
            mma_f16(acc[0][nb * 2 + 0], a[0], b0, b1);
            mma_f16(acc[0][nb * 2 + 1], a[0], b2, b3);
            mma_f16(acc[1][nb * 2 + 0], a[1], b0, b1);
            mma_f16(acc[1][nb * 2 + 1], a[1], b2, b3);
        }
    }

    __half* Ehp = Eh + (size_t)bh * SEQ * SEQ;
#pragma unroll
    for (int mf = 0; mf < 2; mf++) {
        int gi = i0 + m0w + mf * 16 + g;
        float rs0 = 0.f, rs1 = 0.f;
#pragma unroll
        for (int nf = 0; nf < 8; nf++) {
            int gj = j0 + n0w + nf * 8 + tc * 2;
            float e0 = __expf(-0.125f * acc[mf][nf].x);
            float e1 = __expf(-0.125f * acc[mf][nf].y);
            float e2 = __expf(-0.125f * acc[mf][nf].z);
            float e3 = __expf(-0.125f * acc[mf][nf].w);
            *(__half2*)(Ehp + (size_t)gi * SEQ + gj) = __floats2half2_rn(e0, e1);
            *(__half2*)(Ehp + (size_t)(gi + 8) * SEQ + gj) = __floats2half2_rn(e2, e3);
            rs0 += e0 + e1; rs1 += e2 + e3;
        }
        rs0 += __shfl_xor_sync(0xffffffffu, rs0, 1);
        rs0 += __shfl_xor_sync(0xffffffffu, rs0, 2);
        rs1 += __shfl_xor_sync(0xffffffffu, rs1, 1);
        rs1 += __shfl_xor_sync(0xffffffffu, rs1, 2);
        if (tc == 0) {
            atomicAdd(&rowsum[bh * SEQ + gi], rs0);
            atomicAdd(&rowsum[bh * SEQ + gi + 8], rs1);
        }
    }
}

// ---- col pass over fp16 E ---------------------------------------------------
__global__ __launch_bounds__(256) void colpass_h(
    const __half* __restrict__ Eh, const float* __restrict__ rvec,
    float* __restrict__ colsum, int recip)
{
    const int bh = blockIdx.y;
    const int i0 = blockIdx.x * 64;
    const int t = threadIdx.x;
    __shared__ float rs[64];
    if (t < 64) {
        float rv = rvec[bh * SEQ + i0 + t];
        rs[t] = recip ? (MU_C / rv) : rv;
    }
    __syncthreads();

    const __half* Ep = Eh + (size_t)bh * SEQ * SEQ + (size_t)i0 * SEQ;
    const int j = t * 4;
    float ax = 0.f, ay = 0.f, az = 0.f, aw = 0.f;
#pragma unroll 8
    for (int i = 0; i < 64; i++) {
        uint2 raw = *(const uint2*)(Ep + (size_t)i * SEQ + j);
        float2 f0 = __half22float2(*(__half2*)&raw.x);
        float2 f1 = __half22float2(*(__half2*)&raw.y);
        float rv = rs[i];
        ax = fmaf(f0.x, rv, ax); ay = fmaf(f0.y, rv, ay);
        az = fmaf(f1.x, rv, az); aw = fmaf(f1.y, rv, aw);
    }
    atomicAdd(&colsum[bh * SEQ + j + 0], ax);
    atomicAdd(&colsum[bh * SEQ + j + 1], ay);
    atomicAdd(&colsum[bh * SEQ + j + 2], az);
    atomicAdd(&colsum[bh * SEQ + j + 3], aw);
}

// ---- fused row+col pass ------------------------------------------------------
__global__ __launch_bounds__(256) void rc_fused_h(
    const __half* __restrict__ Eh, const float* __restrict__ cs_in,
    float* __restrict__ cs_out, float* __restrict__ rvec)
{
    __shared__ float cs[SEQ];
    __shared__ float rl[32];
    const int bh = blockIdx.y, i0 = blockIdx.x * 32;
    const int t = threadIdx.x, lane = t & 31, w = t >> 5;

#pragma unroll
    for (int q = 0; q < 4; q++) {
        int j = t + 256 * q;
        cs[j] = NU_C / cs_in[bh * SEQ + j];
    }
    __syncthreads();

    const __half* Ep = Eh + (size_t)bh * SEQ * SEQ + (size_t)i0 * SEQ;

#pragma unroll
    for (int rr = 0; rr < 4; rr++) {
        const int row = w * 4 + rr;
        const __half* Er = Ep + (size_t)row * SEQ;
        float acc = 0.f;
#pragma unroll
        for (int it = 0; it < 4; it++) {
            int j = it * 256 + lane * 8;
            uint4 raw = *(const uint4*)(Er + j);
            const __half2* hp = (const __half2*)&raw;
#pragma unroll
            for (int p = 0; p < 4; p++) {
                float2 f = __half22float2(hp[p]);
                acc += f.x * cs[j + p * 2] + f.y * cs[j + p * 2 + 1];
            }
        }
#pragma unroll
        for (int o = 16; o > 0; o >>= 1)
            acc += __shfl_xor_sync(0xffffffffu, acc, o);
        if (lane == 0) {
            float rv = MU_C / acc;
            rl[row] = rv;
            rvec[bh * SEQ + i0 + row] = rv;
        }
    }
    __syncthreads();

    const int j = t * 4;
    float ax = 0.f, ay = 0.f, az = 0.f, aw = 0.f;
#pragma unroll 8
    for (int i = 0; i < 32; i++) {
        uint2 raw = *(const uint2*)(Ep + (size_t)i * SEQ + j);
        float2 f0 = __half22float2(*(__half2*)&raw.x);
        float2 f1 = __half22float2(*(__half2*)&raw.y);
        float rv = rl[i];
        ax = fmaf(f0.x, rv, ax); ay = fmaf(f0.y, rv, ay);
        az = fmaf(f1.x, rv, az); aw = fmaf(f1.y, rv, aw);
    }
    atomicAdd(&cs_out[bh * SEQ + j + 0], ax);
    atomicAdd(&cs_out[bh * SEQ + j + 1], ay);
    atomicAdd(&cs_out[bh * SEQ + j + 2], az);
    atomicAdd(&cs_out[bh * SEQ + j + 3], aw);
}

// --- per-head AV (fp16 mma, BK=64, static smem — R13 shape) ------------------
__global__ __launch_bounds__(256) void av_gemm(
    const __half* __restrict__ Eh, const float* __restrict__ r,
    const float* __restrict__ colsum3, const __half* __restrict__ qkv,
    float* __restrict__ attn, __half* __restrict__ ho, int write_attn)
{
    __shared__ __half Es[128 * 72];   // [i][j-chunk], 64 j + 8 pad
    __shared__ __half Vs[64 * 72];    // [j][d]
    __shared__ float cr[SEQ];
    __shared__ float rn[128];

    const int bh = blockIdx.y, b = bh >> 3, h = bh & 7;
    const int i0 = blockIdx.x * 128;
    const int t = threadIdx.x;
    const int lane = t & 31, w = t >> 5;
    const int wm = w & 3, wn = w >> 2;
    const int g = lane >> 2, tc = lane & 3;
    const int m0w = wm * 32, n0w = wn * 32;

    if (t < 128) rn[t] = r[bh * SEQ + i0 + t] * 1024.0f;
#pragma unroll
    for (int q = 0; q < 4; q++) {
        int j = t + 256 * q;
        cr[j] = NU_C / colsum3[bh * SEQ + j];
    }
    __syncthreads();

    const __half* Ep = Eh + (size_t)bh * SEQ * SEQ;
    const __half* vb = qkv + (size_t)b * SEQ * QKVW + 1024 + h * DHEAD;
    float* ap = attn + (size_t)bh * SEQ * SEQ;

    float4 acc[2][4];
#pragma unroll
    for (int mf = 0; mf < 2; mf++)
#pragma unroll
        for (int nf = 0; nf < 4; nf++) acc[mf][nf] = make_float4(0.f, 0.f, 0.f, 0.f);

    const u32 aAddrBase = sptr(Es) + ((lane & 15) * 72 + ((lane >> 4) << 3)) * 2;
    const u32 bAddrBase = sptr(Vs) +
        ((((lane >> 3) & 1) * 8 + (lane & 7)) * 72 + ((lane >> 4) << 3)) * 2;

    for (int jt = 0; jt < 16; jt++) {
        const int j0 = jt * 64;
#pragma unroll
        for (int q = 0; q < 4; q++) {
            int f = t + 256 * q;
            int i = f >> 3, c8 = (f & 7) * 8;
            uint4 raw = *(const uint4*)(Ep + (size_t)(i0 + i) * SEQ + j0 + c8);
            *(uint4*)(Es + i * 72 + c8) = raw;
            if (write_attn) {
                float rv = rn[i];
                const __half2* hp = (const __half2*)&raw;
                float* dst = ap + (size_t)(i0 + i) * SEQ + j0 + c8;
#pragma unroll
                for (int p = 0; p < 4; p++) {
                    float2 e = __half22float2(hp[p]);
                    float2 o;
                    o.x = rv * e.x * cr[j0 + c8 + p * 2];
                    o.y = rv * e.y * cr[j0 + c8 + p * 2 + 1];
                    *(float2*)(dst + p * 2) = o;
                }
            }
        }
#pragma unroll
        for (int q = 0; q < 2; q++) {
            int f = t + 256 * q;
            int row = f >> 3, c8 = (f & 7) * 8;
            uint4 raw = *(const uint4*)(vb + (size_t)(j0 + row) * QKVW + c8);
            float cw = cr[j0 + row];
            const __half2* hp = (const __half2*)&raw;
            __half2* dst = (__half2*)(Vs + row * 72 + c8);
#pragma unroll
            for (int p = 0; p < 4; p++) {
                float2 v = __half22float2(hp[p]);
                dst[p] = __floats2half2_rn(v.x * cw, v.y * cw);
            }
        }
        __syncthreads();
#pragma unroll
        for (int ks = 0; ks < 64; ks += 16) {
            u32 a[2][4];
#pragma unroll
            for (int mf = 0; mf < 2; mf++)
                ldsm_x4(a[mf][0], a[mf][1], a[mf][2], a[mf][3],
                        aAddrBase + ((m0w + mf * 16) * 72 + ks) * 2);
#pragma unroll
            for (int nb = 0; nb < 2; nb++) {
                u32 b0, b1, b2, b3;
                ldsm_x4t(b0, b1, b2, b3,
                         bAddrBase + (ks * 72 + n0w + nb * 16) * 2);
                mma_f16(acc[0][nb * 2 + 0], a[0], b0, b1);
                mma_f16(acc[0][nb * 2 + 1], a[0], b2, b3);
                mma_f16(acc[1][nb * 2 + 0], a[1], b0, b1);
                mma_f16(acc[1][nb * 2 + 1], a[1], b2, b3);
            }
        }
        __syncthreads();
    }
#pragma unroll
    for (int mf = 0; mf < 2; mf++) {
        int il = m0w + mf * 16 + g;
        float rv0 = rn[il], rv1 = rn[il + 8];
        __half* hp0 = ho + (size_t)(b * SEQ + i0 + il) * DIMV + h * DHEAD;
        __half* hp1 = ho + (size_t)(b * SEQ + i0 + il + 8) * DIMV + h * DHEAD;
#pragma unroll
        for (int nf = 0; nf < 4; nf++) {
            int gc = n0w + nf * 8 + tc * 2;
            *(__half2*)(hp0 + gc) =
                __floats2half2_rn(acc[mf][nf].x * rv0, acc[mf][nf].y * rv0);
            *(__half2*)(hp1 + gc) =
                __floats2half2_rn(acc[mf][nf].z * rv1, acc[mf][nf].w * rv1);
        }
    }
}

// ---------------- launcher ---------------------------------------------------
extern "C" void kernel_launch(void* const* d_in, const int* in_sizes, int n_in,
                              void* d_out, int out_size)
{
    const float* x    = (const float*)d_in[0];
    const float* Wqkv = (const float*)d_in[1];
    const float* Wout = (const float*)d_in[2];
    const float* bout = (const float*)d_in[3];
    float* out = (float*)d_out;

    float *rp, *rsp, *c1p, *c2p, *c3p;
    __half *xh, *wqh, *woh, *qkvp, *Ehp, *hop;
    cudaGetSymbolAddress((void**)&xh,   g_xh);
    cudaGetSymbolAddress((void**)&wqh,  g_wqh);
    cudaGetSymbolAddress((void**)&woh,  g_woh);
    cudaGetSymbolAddress((void**)&qkvp, g_qkv);
    cudaGetSymbolAddress((void**)&Ehp,  g_Eh);
    cudaGetSymbolAddress((void**)&rp,   g_r);
    cudaGetSymbolAddress((void**)&rsp,  g_rowsum);
    cudaGetSymbolAddress((void**)&c1p,  g_cs1);
    cudaGetSymbolAddress((void**)&c2p,  g_cs2);
    cudaGetSymbolAddress((void**)&c3p,  g_cs3);
    cudaGetSymbolAddress((void**)&hop,  g_ho);

    const size_t FIN = (size_t)BQ * SEQ * DIMV;
    const size_t ATT = (size_t)NHEADS * SEQ * SEQ;
    float* fin_ptr = 0;
    float* attn_ptr = 0;
    if ((size_t)out_size >= FIN + ATT) { fin_ptr = out; attn_ptr = out + FIN; }
    else if ((size_t)out_size == ATT)  { attn_ptr = out; }
    else                               { fin_ptr = out; }

    // 0) fp32 -> fp16 operand conversion + accumulator zeroing
    prep<<<592, 256>>>(x, Wqkv, Wout, xh, wqh, woh, rsp, c1p, c2p, c3p);

    // 1) qkv = x @ W_qkv  (pure fp16 mma, double-buffered)
    gemm_hh<1><<<dim3(QKVW / 128, (BQ * SEQ) / 128), 256>>>(
        xh, wqh, qkvp, BQ * SEQ, QKVW, DIMV, (const float*)0);

    // 2) E = exp(-scale*q k^T) fp16, fused rowsum (c0 = 1)
    qk_dots_exp<<<dim3(SEQ / 128, SEQ / 128, NHEADS), 256>>>(qkvp, Ehp, rsp);

    // 3) Sinkhorn: col1, then two fused (row+col) passes
    colpass_h<<<dim3(SEQ / 64, NHEADS), 256>>>(Ehp, rsp, c1p, 1);
    rc_fused_h<<<dim3(SEQ / 32, NHEADS), 256>>>(Ehp, c1p, c2p, rp);   // r2, cs2
    rc_fused_h<<<dim3(SEQ / 32, NHEADS), 256>>>(Ehp, c2p, c3p, rp);   // r3, cs3

    // 4) attn = r*E*c*n (fused fp32 write) and ho = attn @ V (fp16 mma, BK=64)
    av_gemm<<<dim3(SEQ / 128, NHEADS), 256>>>(
        Ehp, rp, c3p, qkvp, attn_ptr ? attn_ptr : (float*)out, hop,
        attn_ptr ? 1 : 0);

    // 5) final = ho @ W_out + b_out  (pure fp16 mma, double-buffered)
    if (fin_ptr)
        gemm_hh<0><<<dim3(DIMV / 128, (BQ * SEQ) / 128), 256>>>(
            hop, woh, fin_ptr, BQ * SEQ, DIMV, DIMV, bout);
}

// round 16
// speedup vs baseline: 1.0252x; 1.0099x over previous
#include <cuda_runtime.h>
#include <cuda_fp16.h>
#include <math.h>

#define BQ 8
#define SEQ 1024
#define DIMV 512
#define HEADS 8
#define DHEAD 64
#define NHEADS 64        // BQ*HEADS
#define QKVW 1536        // 3*HEADS*DHEAD

#define MU_C (1.0f/1024.0f)
#define NU_C (1.0f/1024.0f)

#define XN   ((size_t)BQ * SEQ * DIMV)     // 4,194,304
#define WQN  ((size_t)DIMV * QKVW)         //   786,432
#define WON  ((size_t)DIMV * DIMV)         //   262,144

typedef unsigned int u32;

__device__ __forceinline__ u32 sptr(const void* p) {
    return (u32)__cvta_generic_to_shared(p);
}
__device__ __forceinline__ void ldsm_x4(u32& r0, u32& r1, u32& r2, u32& r3, u32 a) {
    asm volatile("ldmatrix.sync.aligned.m8n8.x4.shared.b16 {%0,%1,%2,%3},[%4];"
        : "=r"(r0), "=r"(r1), "=r"(r2), "=r"(r3) : "r"(a));
}
__device__ __forceinline__ void ldsm_x4t(u32& r0, u32& r1, u32& r2, u32& r3, u32 a) {
    asm volatile("ldmatrix.sync.aligned.m8n8.x4.trans.shared.b16 {%0,%1,%2,%3},[%4];"
        : "=r"(r0), "=r"(r1), "=r"(r2), "=r"(r3) : "r"(a));
}
__device__ __forceinline__ void mma_f16(float4& d, const u32* a, u32 b0, u32 b1) {
    asm volatile(
        "mma.sync.aligned.m16n8k16.row.col.f32.f16.f16.f32 "
        "{%0,%1,%2,%3},{%4,%5,%6,%7},{%8,%9},{%0,%1,%2,%3};"
        : "+f"(d.x), "+f"(d.y), "+f"(d.z), "+f"(d.w)
        : "r"(a[0]), "r"(a[1]), "r"(a[2]), "r"(a[3]), "r"(b0), "r"(b1));
}

// ---------------- scratch (device globals; no allocations allowed) ----------
__device__ __half g_xh[XN];                           // fp16 x
__device__ __half g_wqh[WQN];                         // fp16 W_qkv
__device__ __half g_woh[WON];                         // fp16 W_out
__device__ __half g_qkv[(size_t)BQ * SEQ * QKVW];     // fp16 qkv
__device__ __half g_Eh[(size_t)NHEADS * SEQ * SEQ];   // E = exp(-C), fp16
__device__ float g_r[NHEADS * SEQ];
__device__ float g_rowsum[NHEADS * SEQ];
__device__ float g_cs1[NHEADS * SEQ];
__device__ float g_cs2[NHEADS * SEQ];
__device__ float g_cs3[NHEADS * SEQ];
__device__ __half g_ho[(size_t)BQ * SEQ * DIMV];      // fp16 head-merged out

// ---- convert x, W_qkv, W_out to fp16; zero the Sinkhorn accumulators -------
__global__ __launch_bounds__(256) void prep(
    const float* __restrict__ x, const float* __restrict__ Wq,
    const float* __restrict__ Wo,
    __half* __restrict__ xh, __half* __restrict__ wqh, __half* __restrict__ woh,
    float* __restrict__ rowsum, float* __restrict__ c1,
    float* __restrict__ c2, float* __restrict__ c3)
{
    const size_t tid = (size_t)blockIdx.x * 256 + threadIdx.x;
    const size_t stride = (size_t)gridDim.x * 256;
    const size_t TOT = (XN + WQN + WON) / 4;
    for (size_t f = tid; f < TOT; f += stride) {
        size_t e = f * 4;
        const float* src; __half* dst; size_t off;
        if (e < XN)            { src = x;  dst = xh;  off = e; }
        else if (e < XN + WQN) { src = Wq; dst = wqh; off = e - XN; }
        else                   { src = Wo; dst = woh; off = e - XN - WQN; }
        float4 v = *(const float4*)(src + off);
        *(__half2*)(dst + off)     = __floats2half2_rn(v.x, v.y);
        *(__half2*)(dst + off + 2) = __floats2half2_rn(v.z, v.w);
    }
    const size_t NV = (size_t)NHEADS * SEQ;
    for (size_t i = tid; i < NV; i += stride) {
        rowsum[i] = 0.f; c1[i] = 0.f; c2[i] = 0.f; c3[i] = 0.f;
    }
}

// ---- fp16 GEMM: A,B fp16 -> C (fp16 or fp32+bias). 128x128, BK=32, dbuf ----
template<int HALF_OUT>
__global__ __launch_bounds__(256) void gemm_hh(
    const __half* __restrict__ A, const __half* __restrict__ Bm,
    void* __restrict__ Cv, int M, int N, int K, const float* __restrict__ bias)
{
    __shared__ __half Ah[2][128 * 40];
    __shared__ __half Bh[2][32 * 136];
    const int t = threadIdx.x;
    const int m0 = blockIdx.y * 128, n0 = blockIdx.x * 128;
    const int lane = t & 31, w = t >> 5;
    const int wm = w & 3, wn = w >> 2;
    const int g = lane >> 2, tc = lane & 3;
    const int m0w = wm * 32, n0w = wn * 64;

    float4 acc[2][8];
#pragma unroll
    for (int mf = 0; mf < 2; mf++)
#pragma unroll
        for (int nf = 0; nf < 8; nf++) acc[mf][nf] = make_float4(0.f, 0.f, 0.f, 0.f);

    uint4 avr[2], bvr[2];
#pragma unroll
    for (int q = 0; q < 2; q++) {
        int f = t + 256 * q;
        avr[q] = *(const uint4*)(A + (size_t)(m0 + (f >> 2)) * K + (f & 3) * 8);
        bvr[q] = *(const uint4*)(Bm + (size_t)(f >> 4) * N + n0 + (f & 15) * 8);
    }
#pragma unroll
    for (int q = 0; q < 2; q++) {
        int f = t + 256 * q;
        *(uint4*)(Ah[0] + (f >> 2) * 40 + (f & 3) * 8) = avr[q];
        *(uint4*)(Bh[0] + (f >> 4) * 136 + (f & 15) * 8) = bvr[q];
    }
    __syncthreads();

    const u32 aAddr0 = sptr(Ah[0]) + ((lane & 15) * 40 + ((lane >> 4) << 3)) * 2;
    const u32 bAddr0 = sptr(Bh[0]) +
        ((((lane >> 3) & 1) * 8 + (lane & 7)) * 136 + ((lane >> 4) << 3)) * 2;
    const u32 bufStepA = 128 * 40 * 2, bufStepB = 32 * 136 * 2;

    const int NT = K / 32;
    for (int kt = 0; kt < NT; kt++) {
        const int buf = kt & 1;
        if (kt + 1 < NT) {
            int ko = (kt + 1) * 32;
#pragma unroll
            for (int q = 0; q < 2; q++) {
                int f = t + 256 * q;
                avr[q] = *(const uint4*)(A + (size_t)(m0 + (f >> 2)) * K + ko + (f & 3) * 8);
                bvr[q] = *(const uint4*)(Bm + (size_t)(ko + (f >> 4)) * N + n0 + (f & 15) * 8);
            }
        }
        const u32 aB = aAddr0 + buf * bufStepA;
        const u32 bB = bAddr0 + buf * bufStepB;
#pragma unroll
        for (int ks = 0; ks < 32; ks += 16) {
            u32 a[2][4];
#pragma unroll
            for (int mf = 0; mf < 2; mf++)
                ldsm_x4(a[mf][0], a[mf][1], a[mf][2], a[mf][3],
                        aB + ((m0w + mf * 16) * 40 + ks) * 2);
#pragma unroll
            for (int nb = 0; nb < 4; nb++) {
                u32 b0, b1, b2, b3;
                ldsm_x4t(b0, b1, b2, b3, bB + (ks * 136 + n0w + nb * 16) * 2);
                mma_f16(acc[0][nb * 2 + 0], a[0], b0, b1);
                mma_f16(acc[0][nb * 2 + 1], a[0], b2, b3);
                mma_f16(acc[1][nb * 2 + 0], a[1], b0, b1);
                mma_f16(acc[1][nb * 2 + 1], a[1], b2, b3);
            }
        }
        if (kt + 1 < NT) {
            const int nb_ = buf ^ 1;
#pragma unroll
            for (int q = 0; q < 2; q++) {
                int f = t + 256 * q;
                *(uint4*)(Ah[nb_] + (f >> 2) * 40 + (f & 3) * 8) = avr[q];
                *(uint4*)(Bh[nb_] + (f >> 4) * 136 + (f & 15) * 8) = bvr[q];
            }
        }
        __syncthreads();
    }
#pragma unroll
    for (int mf = 0; mf < 2; mf++) {
        int gr = m0 + m0w + mf * 16 + g;
#pragma unroll
        for (int nf = 0; nf < 8; nf++) {
            int gc = n0 + n0w + nf * 8 + tc * 2;
            if (HALF_OUT) {
                __half* C = (__half*)Cv;
                *(__half2*)(C + (size_t)gr * N + gc) =
                    __floats2half2_rn(acc[mf][nf].x, acc[mf][nf].y);
                *(__half2*)(C + (size_t)(gr + 8) * N + gc) =
                    __floats2half2_rn(acc[mf][nf].z, acc[mf][nf].w);
            } else {
                float* C = (float*)Cv;
                float2 lo = make_float2(acc[mf][nf].x + bias[gc],
                                        acc[mf][nf].y + bias[gc + 1]);
                float2 hi = make_float2(acc[mf][nf].z + bias[gc],
                                        acc[mf][nf].w + bias[gc + 1]);
                *(float2*)(C + (size_t)gr * N + gc) = lo;
                *(float2*)(C + (size_t)(gr + 8) * N + gc) = hi;
            }
        }
    }
}

// ------- dots (fp16 mma): E = exp(-scale*q k^T) fp16, fused row-sum ---------
// E written via smem staging for fully coalesced uint4 stores.
__global__ __launch_bounds__(256) void qk_dots_exp(
    const __half* __restrict__ qkv, __half* __restrict__ Eh,
    float* __restrict__ rowsum)
{
    __shared__ __half sh[2 * 128 * 72];   // Ah/Bh; reused as Est[128*136]
    __half* Ah = sh;
    __half* Bh = sh + 128 * 72;
    const int bh = blockIdx.z, b = bh >> 3, h = bh & 7;
    const int i0 = blockIdx.y * 128, j0 = blockIdx.x * 128;
    const __half* qbase = qkv + (size_t)b * SEQ * QKVW + h * DHEAD;
    const __half* kbase = qkv + (size_t)b * SEQ * QKVW + 512 + h * DHEAD;

    const int t = threadIdx.x;
    const int lane = t & 31, w = t >> 5;
    const int wm = w & 3, wn = w >> 2;
    const int g = lane >> 2, tc = lane & 3;
    const int m0w = wm * 32, n0w = wn * 64;

    float4 acc[2][8];
#pragma unroll
    for (int mf = 0; mf < 2; mf++)
#pragma unroll
        for (int nf = 0; nf < 8; nf++) acc[mf][nf] = make_float4(0.f, 0.f, 0.f, 0.f);

#pragma unroll
    for (int q = 0; q < 4; q++) {
        int f = t + 256 * q;
        int row = f >> 3, c8 = (f & 7) * 8;
        *(uint4*)(Ah + row * 72 + c8) =
            *(const uint4*)(qbase + (size_t)(i0 + row) * QKVW + c8);
        *(uint4*)(Bh + row * 72 + c8) =
            *(const uint4*)(kbase + (size_t)(j0 + row) * QKVW + c8);
    }
    __syncthreads();

    const u32 aAddrBase = sptr(Ah) + ((lane & 15) * 72 + ((lane >> 4) << 3)) * 2;
    const u32 bAddrBase = sptr(Bh) +
        ((((lane >> 4) << 3) + (lane & 7)) * 72 + (((lane >> 3) & 1) * 8)) * 2;

#pragma unroll
    for (int ks = 0; ks < 64; ks += 16) {
        u32 a[2][4];
#pragma unroll
        for (int mf = 0; mf < 2; mf++)
            ldsm_x4(a[mf][0], a[mf][1], a[mf][2], a[mf][3],
                    aAddrBase + ((m0w + mf * 16) * 72 + ks) * 2);
#pragma unroll
        for (int nb = 0; nb < 4; nb++) {
            u32 b0, b1, b2, b3;
            ldsm_x4(b0, b1, b2, b3,
                    bAddrBase + ((n0w + nb * 16) * 72 + ks) * 2);
            mma_f16(acc[0][nb * 2 + 0], a[0], b0, b1);
            mma_f16(acc[0][nb * 2 + 1], a[0], b2, b3);
            mma_f16(acc[1][nb * 2 + 0], a[1], b0, b1);
            mma_f16(acc[1][nb * 2 + 1], a[1], b2, b3);
        }
    }
    __syncthreads();   // mma done; safe to reuse sh as Est

    // stage exp(E) in smem [128 x 136 halves], accumulate rowsums
    __half* Est = sh;
#pragma unroll
    for (int mf = 0; mf < 2; mf++) {
        int r0 = m0w + mf * 16 + g;
        float rs0 = 0.f, rs1 = 0.f;
#pragma unroll
        for (int nf = 0; nf < 8; nf++) {
            int col = n0w + nf * 8 + tc * 2;
            float e0 = __expf(-0.125f * acc[mf][nf].x);
            float e1 = __expf(-0.125f * acc[mf][nf].y);
            float e2 = __expf(-0.125f * acc[mf][nf].z);
            float e3 = __expf(-0.125f * acc[mf][nf].w);
            *(__half2*)(Est + r0 * 136 + col)       = __floats2half2_rn(e0, e1);
            *(__half2*)(Est + (r0 + 8) * 136 + col) = __floats2half2_rn(e2, e3);
            rs0 += e0 + e1; rs1 += e2 + e3;
        }
        rs0 += __shfl_xor_sync(0xffffffffu, rs0, 1);
        rs0 += __shfl_xor_sync(0xffffffffu, rs0, 2);
        rs1 += __shfl_xor_sync(0xffffffffu, rs1, 1);
        rs1 += __shfl_xor_sync(0xffffffffu, rs1, 2);
        if (tc == 0) {
            atomicAdd(&rowsum[bh * SEQ + i0 + r0], rs0);
            atomicAdd(&rowsum[bh * SEQ + i0 + r0 + 8], rs1);
        }
    }
    __syncthreads();

    // coalesced E write: 256B contiguous per 16 lanes
    __half* Ehp = Eh + (size_t)bh * SEQ * SEQ;
#pragma unroll
    for (int q = 0; q < 8; q++) {
        int f = t + 256 * q;
        int row = f >> 4, c8 = (f & 15) * 8;
        *(uint4*)(Ehp + (size_t)(i0 + row) * SEQ + j0 + c8) =
            *(const uint4*)(Est + row * 136 + c8);
    }
}

// ---- col pass over fp16 E ---------------------------------------------------
__global__ __launch_bounds__(256) void colpass_h(
    const __half* __restrict__ Eh, const float* __restrict__ rvec,
    float* __restrict__ colsum, int recip)
{
    const int bh = blockIdx.y;
    const int i0 = blockIdx.x * 64;
    const int t = threadIdx.x;
    __shared__ float rs[64];
    if (t < 64) {
        float rv = rvec[bh * SEQ + i0 + t];
        rs[t] = recip ? (MU_C / rv) : rv;
    }
    __syncthreads();

    const __half* Ep = Eh + (size_t)bh * SEQ * SEQ + (size_t)i0 * SEQ;
    const int j = t * 4;
    float ax = 0.f, ay = 0.f, az = 0.f, aw = 0.f;
#pragma unroll 8
    for (int i = 0; i < 64; i++) {
        uint2 raw = *(const uint2*)(Ep + (size_t)i * SEQ + j);
        float2 f0 = __half22float2(*(__half2*)&raw.x);
        float2 f1 = __half22float2(*(__half2*)&raw.y);
        float rv = rs[i];
        ax = fmaf(f0.x, rv, ax); ay = fmaf(f0.y, rv, ay);
        az = fmaf(f1.x, rv, az); aw = fmaf(f1.y, rv, aw);
    }
    atomicAdd(&colsum[bh * SEQ + j + 0], ax);
    atomicAdd(&colsum[bh * SEQ + j + 1], ay);
    atomicAdd(&colsum[bh * SEQ + j + 2], az);
    atomicAdd(&colsum[bh * SEQ + j + 3], aw);
}

// ---- fused row+col pass ------------------------------------------------------
__global__ __launch_bounds__(256) void rc_fused_h(
    const __half* __restrict__ Eh, const float* __restrict__ cs_in,
    float* __restrict__ cs_out, float* __restrict__ rvec)
{
    __shared__ float cs[SEQ];
    __shared__ float rl[32];
    const int bh = blockIdx.y, i0 = blockIdx.x * 32;
    const int t = threadIdx.x, lane = t & 31, w = t >> 5;

#pragma unroll
    for (int q = 0; q < 4; q++) {
        int j = t + 256 * q;
        cs[j] = NU_C / cs_in[bh * SEQ + j];
    }
    __syncthreads();

    const __half* Ep = Eh + (size_t)bh * SEQ * SEQ + (size_t)i0 * SEQ;

#pragma unroll
    for (int rr = 0; rr < 4; rr++) {
        const int row = w * 4 + rr;
        const __half* Er = Ep + (size_t)row * SEQ;
        float acc = 0.f;
#pragma unroll
        for (int it = 0; it < 4; it++) {
            int j = it * 256 + lane * 8;
            uint4 raw = *(const uint4*)(Er + j);
            const __half2* hp = (const __half2*)&raw;
#pragma unroll
            for (int p = 0; p < 4; p++) {
                float2 f = __half22float2(hp[p]);
                acc += f.x * cs[j + p * 2] + f.y * cs[j + p * 2 + 1];
            }
        }
#pragma unroll
        for (int o = 16; o > 0; o >>= 1)
            acc += __shfl_xor_sync(0xffffffffu, acc, o);
        if (lane == 0) {
            float rv = MU_C / acc;
            rl[row] = rv;
            rvec[bh * SEQ + i0 + row] = rv;
        }
    }
    __syncthreads();

    const int j = t * 4;
    float ax = 0.f, ay = 0.f, az = 0.f, aw = 0.f;
#pragma unroll 8
    for (int i = 0; i < 32; i++) {
        uint2 raw = *(const uint2*)(Ep + (size_t)i * SEQ + j);
        float2 f0 = __half22float2(*(__half2*)&raw.x);
        float2 f1 = __half22float2(*(__half2*)&raw.y);
        float rv = rl[i];
        ax = fmaf(f0.x, rv, ax); ay = fmaf(f0.y, rv, ay);
        az = fmaf(f1.x, rv, az); aw = fmaf(f1.y, rv, aw);
    }
    atomicAdd(&cs_out[bh * SEQ + j + 0], ax);
    atomicAdd(&cs_out[bh * SEQ + j + 1], ay);
    atomicAdd(&cs_out[bh * SEQ + j + 2], az);
    atomicAdd(&cs_out[bh * SEQ + j + 3], aw);
}

// --- per-head AV (fp16 mma, BK=64, static smem) ------------------------------
__global__ __launch_bounds__(256) void av_gemm(
    const __half* __restrict__ Eh, const float* __restrict__ r,
    const float* __restrict__ colsum3, const __half* __restrict__ qkv,
    float* __restrict__ attn, __half* __restrict__ ho, int write_attn)
{
    __shared__ __half Es[128 * 72];   // [i][j-chunk], 64 j + 8 pad
    __shared__ __half Vs[64 * 72];    // [j][d]
    __shared__ float cr[SEQ];
    __shared__ float rn[128];

    const int bh = blockIdx.y, b = bh >> 3, h = bh & 7;
    const int i0 = blockIdx.x * 128;
    const int t = threadIdx.x;
    const int lane = t & 31, w = t >> 5;
    const int wm = w & 3, wn = w >> 2;
    const int g = lane >> 2, tc = lane & 3;
    const int m0w = wm * 32, n0w = wn * 32;

    if (t < 128) rn[t] = r[bh * SEQ + i0 + t] * 1024.0f;
#pragma unroll
    for (int q = 0; q < 4; q++) {
        int j = t + 256 * q;
        cr[j] = NU_C / colsum3[bh * SEQ + j];
    }
    __syncthreads();

    const __half* Ep = Eh + (size_t)bh * SEQ * SEQ;
    const __half* vb = qkv + (size_t)b * SEQ * QKVW + 1024 + h * DHEAD;
    float* ap = attn + (size_t)bh * SEQ * SEQ;

    float4 acc[2][4];
#pragma unroll
    for (int mf = 0; mf < 2; mf++)
#pragma unroll
        for (int nf = 0; nf < 4; nf++) acc[mf][nf] = make_float4(0.f, 0.f, 0.f, 0.f);

    const u32 aAddrBase = sptr(Es) + ((lane & 15) * 72 + ((lane >> 4) << 3)) * 2;
    const u32 bAddrBase = sptr(Vs) +
        ((((lane >> 3) & 1) * 8 + (lane & 7)) * 72 + ((lane >> 4) << 3)) * 2;

    for (int jt = 0; jt < 16; jt++) {
        const int j0 = jt * 64;
#pragma unroll
        for (int q = 0; q < 4; q++) {
            int f = t + 256 * q;
            int i = f >> 3, c8 = (f & 7) * 8;
            uint4 raw = *(const uint4*)(Ep + (size_t)(i0 + i) * SEQ + j0 + c8);
            *(uint4*)(Es + i * 72 + c8) = raw;
            if (write_attn) {
                float rv = rn[i];
                const __half2* hp = (const __half2*)&raw;
                float* dst = ap + (size_t)(i0 + i) * SEQ + j0 + c8;
#pragma unroll
                for (int p = 0; p < 4; p++) {
                    float2 e = __half22float2(hp[p]);
                    float2 o;
                    o.x = rv * e.x * cr[j0 + c8 + p * 2];
                    o.y = rv * e.y * cr[j0 + c8 + p * 2 + 1];
                    *(float2*)(dst + p * 2) = o;
                }
            }
        }
#pragma unroll
        for (int q = 0; q < 2; q++) {
            int f = t + 256 * q;
            int row = f >> 3, c8 = (f & 7) * 8;
            uint4 raw = *(const uint4*)(vb + (size_t)(j0 + row) * QKVW + c8);
            float cw = cr[j0 + row];
            const __half2* hp = (const __half2*)&raw;
            __half2* dst = (__half2*)(Vs + row * 72 + c8);
#pragma unroll
            for (int p = 0; p < 4; p++) {
                float2 v = __half22float2(hp[p]);
                dst[p] = __floats2half2_rn(v.x * cw, v.y * cw);
            }
        }
        __syncthreads();
#pragma unroll
        for (int ks = 0; ks < 64; ks += 16) {
            u32 a[2][4];
#pragma unroll
            for (int mf = 0; mf < 2; mf++)
                ldsm_x4(a[mf][0], a[mf][1], a[mf][2], a[mf][3],
                        aAddrBase + ((m0w + mf * 16) * 72 + ks) * 2);
#pragma unroll
            for (int nb = 0; nb < 2; nb++) {
                u32 b0, b1, b2, b3;
                ldsm_x4t(b0, b1, b2, b3,
                         bAddrBase + (ks * 72 + n0w + nb * 16) * 2);
                mma_f16(acc[0][nb * 2 + 0], a[0], b0, b1);
                mma_f16(acc[0][nb * 2 + 1], a[0], b2, b3);
                mma_f16(acc[1][nb * 2 + 0], a[1], b0, b1);
                mma_f16(acc[1][nb * 2 + 1], a[1], b2, b3);
            }
        }
        __syncthreads();
    }
#pragma unroll
    for (int mf = 0; mf < 2; mf++) {
        int il = m0w + mf * 16 + g;
        float rv0 = rn[il], rv1 = rn[il + 8];
        __half* hp0 = ho + (size_t)(b * SEQ + i0 + il) * DIMV + h * DHEAD;
        __half* hp1 = ho + (size_t)(b * SEQ + i0 + il + 8) * DIMV + h * DHEAD;
#pragma unroll
        for (int nf = 0; nf < 4; nf++) {
            int gc = n0w + nf * 8 + tc * 2;
            *(__half2*)(hp0 + gc) =
                __floats2half2_rn(acc[mf][nf].x * rv0, acc[mf][nf].y * rv0);
            *(__half2*)(hp1 + gc) =
                __floats2half2_rn(acc[mf][nf].z * rv1, acc[mf][nf].w * rv1);
        }
    }
}

// ---------------- launcher ---------------------------------------------------
extern "C" void kernel_launch(void* const* d_in, const int* in_sizes, int n_in,
                              void* d_out, int out_size)
{
    const float* x    = (const float*)d_in[0];
    const float* Wqkv = (const float*)d_in[1];
    const float* Wout = (const float*)d_in[2];
    const float* bout = (const float*)d_in[3];
    float* out = (float*)d_out;

    float *rp, *rsp, *c1p, *c2p, *c3p;
    __half *xh, *wqh, *woh, *qkvp, *Ehp, *hop;
    cudaGetSymbolAddress((void**)&xh,   g_xh);
    cudaGetSymbolAddress((void**)&wqh,  g_wqh);
    cudaGetSymbolAddress((void**)&woh,  g_woh);
    cudaGetSymbolAddress((void**)&qkvp, g_qkv);
    cudaGetSymbolAddress((void**)&Ehp,  g_Eh);
    cudaGetSymbolAddress((void**)&rp,   g_r);
    cudaGetSymbolAddress((void**)&rsp,  g_rowsum);
    cudaGetSymbolAddress((void**)&c1p,  g_cs1);
    cudaGetSymbolAddress((void**)&c2p,  g_cs2);
    cudaGetSymbolAddress((void**)&c3p,  g_cs3);
    cudaGetSymbolAddress((void**)&hop,  g_ho);

    const size_t FIN = (size_t)BQ * SEQ * DIMV;
    const size_t ATT = (size_t)NHEADS * SEQ * SEQ;
    float* fin_ptr = 0;
    float* attn_ptr = 0;
    if ((size_t)out_size >= FIN + ATT) { fin_ptr = out; attn_ptr = out + FIN; }
    else if ((size_t)out_size == ATT)  { attn_ptr = out; }
    else                               { fin_ptr = out; }

    // 0) fp32 -> fp16 operand conversion + accumulator zeroing
    prep<<<592, 256>>>(x, Wqkv, Wout, xh, wqh, woh, rsp, c1p, c2p, c3p);

    // 1) qkv = x @ W_qkv  (pure fp16 mma, double-buffered)
    gemm_hh<1><<<dim3(QKVW / 128, (BQ * SEQ) / 128), 256>>>(
        xh, wqh, qkvp, BQ * SEQ, QKVW, DIMV, (const float*)0);

    // 2) E = exp(-scale*q k^T) fp16 (coalesced stores), fused rowsum
    qk_dots_exp<<<dim3(SEQ / 128, SEQ / 128, NHEADS), 256>>>(qkvp, Ehp, rsp);

    // 3) Sinkhorn: col1, then two fused (row+col) passes
    colpass_h<<<dim3(SEQ / 64, NHEADS), 256>>>(Ehp, rsp, c1p, 1);
    rc_fused_h<<<dim3(SEQ / 32, NHEADS), 256>>>(Ehp, c1p, c2p, rp);   // r2, cs2
    rc_fused_h<<<dim3(SEQ / 32, NHEADS), 256>>>(Ehp, c2p, c3p, rp);   // r3, cs3

    // 4) attn = r*E*c*n (fused fp32 write) and ho = attn @ V (fp16 mma, BK=64)
    av_gemm<<<dim3(SEQ / 128, NHEADS), 256>>>(
        Ehp, rp, c3p, qkvp, attn_ptr ? attn_ptr : (float*)out, hop,
        attn_ptr ? 1 : 0);

    // 5) final = ho @ W_out + b_out  (pure fp16 mma, double-buffered)
    if (fin_ptr)
        gemm_hh<0><<<dim3(DIMV / 128, (BQ * SEQ) / 128), 256>>>(
            hop, woh, fin_ptr, BQ * SEQ, DIMV, DIMV, bout);
}

// round 17
// speedup vs baseline: 1.0529x; 1.0270x over previous
#include <cuda_runtime.h>
#include <cuda_fp16.h>
#include <math.h>

#define BQ 8
#define SEQ 1024
#define DIMV 512
#define HEADS 8
#define DHEAD 64
#define NHEADS 64        // BQ*HEADS
#define QKVW 1536        // 3*HEADS*DHEAD

#define MU_C (1.0f/1024.0f)
#define NU_C (1.0f/1024.0f)

#define XN   ((size_t)BQ * SEQ * DIMV)     // 4,194,304
#define WQN  ((size_t)DIMV * QKVW)         //   786,432
#define WON  ((size_t)DIMV * DIMV)         //   262,144

typedef unsigned int u32;

__device__ __forceinline__ u32 sptr(const void* p) {
    return (u32)__cvta_generic_to_shared(p);
}
__device__ __forceinline__ void ldsm_x4(u32& r0, u32& r1, u32& r2, u32& r3, u32 a) {
    asm volatile("ldmatrix.sync.aligned.m8n8.x4.shared.b16 {%0,%1,%2,%3},[%4];"
        : "=r"(r0), "=r"(r1), "=r"(r2), "=r"(r3) : "r"(a));
}
__device__ __forceinline__ void ldsm_x4t(u32& r0, u32& r1, u32& r2, u32& r3, u32 a) {
    asm volatile("ldmatrix.sync.aligned.m8n8.x4.trans.shared.b16 {%0,%1,%2,%3},[%4];"
        : "=r"(r0), "=r"(r1), "=r"(r2), "=r"(r3) : "r"(a));
}
__device__ __forceinline__ void mma_f16(float4& d, const u32* a, u32 b0, u32 b1) {
    asm volatile(
        "mma.sync.aligned.m16n8k16.row.col.f32.f16.f16.f32 "
        "{%0,%1,%2,%3},{%4,%5,%6,%7},{%8,%9},{%0,%1,%2,%3};"
        : "+f"(d.x), "+f"(d.y), "+f"(d.z), "+f"(d.w)
        : "r"(a[0]), "r"(a[1]), "r"(a[2]), "r"(a[3]), "r"(b0), "r"(b1));
}

// ---------------- scratch (device globals; no allocations allowed) ----------
__device__ __half g_xh[XN];                           // fp16 x
__device__ __half g_wqh[WQN];                         // fp16 W_qkv
__device__ __half g_woh[WON];                         // fp16 W_out
__device__ __half g_qkv[(size_t)BQ * SEQ * QKVW];     // fp16 qkv
__device__ __half g_Eh[(size_t)NHEADS * SEQ * SEQ];   // E = exp(-C), fp16
__device__ float g_r[NHEADS * SEQ];
__device__ float g_rowsum[NHEADS * SEQ];
__device__ float g_cs1[NHEADS * SEQ];
__device__ float g_cs2[NHEADS * SEQ];
__device__ float g_cs3[NHEADS * SEQ];
__device__ __half g_ho[(size_t)BQ * SEQ * DIMV];      // fp16 head-merged out

// ---- convert x, W_qkv, W_out to fp16; zero the Sinkhorn accumulators -------
__global__ __launch_bounds__(256) void prep(
    const float* __restrict__ x, const float* __restrict__ Wq,
    const float* __restrict__ Wo,
    __half* __restrict__ xh, __half* __restrict__ wqh, __half* __restrict__ woh,
    float* __restrict__ rowsum, float* __restrict__ c1,
    float* __restrict__ c2, float* __restrict__ c3)
{
    const size_t tid = (size_t)blockIdx.x * 256 + threadIdx.x;
    const size_t stride = (size_t)gridDim.x * 256;
    const size_t TOT = (XN + WQN + WON) / 4;
    for (size_t f = tid; f < TOT; f += stride) {
        size_t e = f * 4;
        const float* src; __half* dst; size_t off;
        if (e < XN)            { src = x;  dst = xh;  off = e; }
        else if (e < XN + WQN) { src = Wq; dst = wqh; off = e - XN; }
        else                   { src = Wo; dst = woh; off = e - XN - WQN; }
        float4 v = *(const float4*)(src + off);
        *(__half2*)(dst + off)     = __floats2half2_rn(v.x, v.y);
        *(__half2*)(dst + off + 2) = __floats2half2_rn(v.z, v.w);
    }
    const size_t NV = (size_t)NHEADS * SEQ;
    for (size_t i = tid; i < NV; i += stride) {
        rowsum[i] = 0.f; c1[i] = 0.f; c2[i] = 0.f; c3[i] = 0.f;
    }
}

// ---- fp16 GEMM: A,B fp16 -> C (fp16 or fp32+bias). 128x128, BK=32, dbuf ----
template<int HALF_OUT>
__global__ __launch_bounds__(256) void gemm_hh(
    const __half* __restrict__ A, const __half* __restrict__ Bm,
    void* __restrict__ Cv, int M, int N, int K, const float* __restrict__ bias)
{
    __shared__ __half Ah[2][128 * 40];
    __shared__ __half Bh[2][32 * 136];
    const int t = threadIdx.x;
    const int m0 = blockIdx.y * 128, n0 = blockIdx.x * 128;
    const int lane = t & 31, w = t >> 5;
    const int wm = w & 3, wn = w >> 2;
    const int g = lane >> 2, tc = lane & 3;
    const int m0w = wm * 32, n0w = wn * 64;

    float4 acc[2][8];
#pragma unroll
    for (int mf = 0; mf < 2; mf++)
#pragma unroll
        for (int nf = 0; nf < 8; nf++) acc[mf][nf] = make_float4(0.f, 0.f, 0.f, 0.f);

    uint4 avr[2], bvr[2];
#pragma unroll
    for (int q = 0; q < 2; q++) {
        int f = t + 256 * q;
        avr[q] = *(const uint4*)(A + (size_t)(m0 + (f >> 2)) * K + (f & 3) * 8);
        bvr[q] = *(const uint4*)(Bm + (size_t)(f >> 4) * N + n0 + (f & 15) * 8);
    }
#pragma unroll
    for (int q = 0; q < 2; q++) {
        int f = t + 256 * q;
        *(uint4*)(Ah[0] + (f >> 2) * 40 + (f & 3) * 8) = avr[q];
        *(uint4*)(Bh[0] + (f >> 4) * 136 + (f & 15) * 8) = bvr[q];
    }
    __syncthreads();

    const u32 aAddr0 = sptr(Ah[0]) + ((lane & 15) * 40 + ((lane >> 4) << 3)) * 2;
    const u32 bAddr0 = sptr(Bh[0]) +
        ((((lane >> 3) & 1) * 8 + (lane & 7)) * 136 + ((lane >> 4) << 3)) * 2;
    const u32 bufStepA = 128 * 40 * 2, bufStepB = 32 * 136 * 2;

    const int NT = K / 32;
    for (int kt = 0; kt < NT; kt++) {
        const int buf = kt & 1;
        if (kt + 1 < NT) {
            int ko = (kt + 1) * 32;
#pragma unroll
            for (int q = 0; q < 2; q++) {
                int f = t + 256 * q;
                avr[q] = *(const uint4*)(A + (size_t)(m0 + (f >> 2)) * K + ko + (f & 3) * 8);
                bvr[q] = *(const uint4*)(Bm + (size_t)(ko + (f >> 4)) * N + n0 + (f & 15) * 8);
            }
        }
        const u32 aB = aAddr0 + buf * bufStepA;
        const u32 bB = bAddr0 + buf * bufStepB;
#pragma unroll
        for (int ks = 0; ks < 32; ks += 16) {
            u32 a[2][4];
#pragma unroll
            for (int mf = 0; mf < 2; mf++)
                ldsm_x4(a[mf][0], a[mf][1], a[mf][2], a[mf][3],
                        aB + ((m0w + mf * 16) * 40 + ks) * 2);
#pragma unroll
            for (int nb = 0; nb < 4; nb++) {
                u32 b0, b1, b2, b3;
                ldsm_x4t(b0, b1, b2, b3, bB + (ks * 136 + n0w + nb * 16) * 2);
                mma_f16(acc[0][nb * 2 + 0], a[0], b0, b1);
                mma_f16(acc[0][nb * 2 + 1], a[0], b2, b3);
                mma_f16(acc[1][nb * 2 + 0], a[1], b0, b1);
                mma_f16(acc[1][nb * 2 + 1], a[1], b2, b3);
            }
        }
        if (kt + 1 < NT) {
            const int nb_ = buf ^ 1;
#pragma unroll
            for (int q = 0; q < 2; q++) {
                int f = t + 256 * q;
                *(uint4*)(Ah[nb_] + (f >> 2) * 40 + (f & 3) * 8) = avr[q];
                *(uint4*)(Bh[nb_] + (f >> 4) * 136 + (f & 15) * 8) = bvr[q];
            }
        }
        __syncthreads();
    }
#pragma unroll
    for (int mf = 0; mf < 2; mf++) {
        int gr = m0 + m0w + mf * 16 + g;
#pragma unroll
        for (int nf = 0; nf < 8; nf++) {
            int gc = n0 + n0w + nf * 8 + tc * 2;
            if (HALF_OUT) {
                __half* C = (__half*)Cv;
                *(__half2*)(C + (size_t)gr * N + gc) =
                    __floats2half2_rn(acc[mf][nf].x, acc[mf][nf].y);
                *(__half2*)(C + (size_t)(gr + 8) * N + gc) =
                    __floats2half2_rn(acc[mf][nf].z, acc[mf][nf].w);
            } else {
                float* C = (float*)Cv;
                float2 lo = make_float2(acc[mf][nf].x + bias[gc],
                                        acc[mf][nf].y + bias[gc + 1]);
                float2 hi = make_float2(acc[mf][nf].z + bias[gc],
                                        acc[mf][nf].w + bias[gc + 1]);
                *(float2*)(C + (size_t)gr * N + gc) = lo;
                *(float2*)(C + (size_t)(gr + 8) * N + gc) = hi;
            }
        }
    }
}

// ------- dots (fp16 mma): E = exp(-scale*q k^T) fp16, fused row-sum ---------
__global__ __launch_bounds__(256) void qk_dots_exp(
    const __half* __restrict__ qkv, __half* __restrict__ Eh,
    float* __restrict__ rowsum)
{
    __shared__ __half sh[2 * 128 * 72];   // Ah/Bh; reused as Est[128*136]
    __half* Ah = sh;
    __half* Bh = sh + 128 * 72;
    const int bh = blockIdx.z, b = bh >> 3, h = bh & 7;
    const int i0 = blockIdx.y * 128, j0 = blockIdx.x * 128;
    const __half* qbase = qkv + (size_t)b * SEQ * QKVW + h * DHEAD;
    const __half* kbase = qkv + (size_t)b * SEQ * QKVW + 512 + h * DHEAD;

    const int t = threadIdx.x;
    const int lane = t & 31, w = t >> 5;
    const int wm = w & 3, wn = w >> 2;
    const int g = lane >> 2, tc = lane & 3;
    const int m0w = wm * 32, n0w = wn * 64;

    float4 acc[2][8];
#pragma unroll
    for (int mf = 0; mf < 2; mf++)
#pragma unroll
        for (int nf = 0; nf < 8; nf++) acc[mf][nf] = make_float4(0.f, 0.f, 0.f, 0.f);

#pragma unroll
    for (int q = 0; q < 4; q++) {
        int f = t + 256 * q;
        int row = f >> 3, c8 = (f & 7) * 8;
        *(uint4*)(Ah + row * 72 + c8) =
            *(const uint4*)(qbase + (size_t)(i0 + row) * QKVW + c8);
        *(uint4*)(Bh + row * 72 + c8) =
            *(const uint4*)(kbase + (size_t)(j0 + row) * QKVW + c8);
    }
    __syncthreads();

    const u32 aAddrBase = sptr(Ah) + ((lane & 15) * 72 + ((lane >> 4) << 3)) * 2;
    const u32 bAddrBase = sptr(Bh) +
        ((((lane >> 4) << 3) + (lane & 7)) * 72 + (((lane >> 3) & 1) * 8)) * 2;

#pragma unroll
    for (int ks = 0; ks < 64; ks += 16) {
        u32 a[2][4];
#pragma unroll
        for (int mf = 0; mf < 2; mf++)
            ldsm_x4(a[mf][0], a[mf][1], a[mf][2], a[mf][3],
                    aAddrBase + ((m0w + mf * 16) * 72 + ks) * 2);
#pragma unroll
        for (int nb = 0; nb < 4; nb++) {
            u32 b0, b1, b2, b3;
            ldsm_x4(b0, b1, b2, b3,
                    bAddrBase + ((n0w + nb * 16) * 72 + ks) * 2);
            mma_f16(acc[0][nb * 2 + 0], a[0], b0, b1);
            mma_f16(acc[0][nb * 2 + 1], a[0], b2, b3);
            mma_f16(acc[1][nb * 2 + 0], a[1], b0, b1);
            mma_f16(acc[1][nb * 2 + 1], a[1], b2, b3);
        }
    }
    __syncthreads();   // mma done; safe to reuse sh as Est

    __half* Est = sh;
#pragma unroll
    for (int mf = 0; mf < 2; mf++) {
        int r0 = m0w + mf * 16 + g;
        float rs0 = 0.f, rs1 = 0.f;
#pragma unroll
        for (int nf = 0; nf < 8; nf++) {
            int col = n0w + nf * 8 + tc * 2;
            float e0 = __expf(-0.125f * acc[mf][nf].x);
            float e1 = __expf(-0.125f * acc[mf][nf].y);
            float e2 = __expf(-0.125f * acc[mf][nf].z);
            float e3 = __expf(-0.125f * acc[mf][nf].w);
            *(__half2*)(Est + r0 * 136 + col)       = __floats2half2_rn(e0, e1);
            *(__half2*)(Est + (r0 + 8) * 136 + col) = __floats2half2_rn(e2, e3);
            rs0 += e0 + e1; rs1 += e2 + e3;
        }
        rs0 += __shfl_xor_sync(0xffffffffu, rs0, 1);
        rs0 += __shfl_xor_sync(0xffffffffu, rs0, 2);
        rs1 += __shfl_xor_sync(0xffffffffu, rs1, 1);
        rs1 += __shfl_xor_sync(0xffffffffu, rs1, 2);
        if (tc == 0) {
            atomicAdd(&rowsum[bh * SEQ + i0 + r0], rs0);
            atomicAdd(&rowsum[bh * SEQ + i0 + r0 + 8], rs1);
        }
    }
    __syncthreads();

    __half* Ehp = Eh + (size_t)bh * SEQ * SEQ;
#pragma unroll
    for (int q = 0; q < 8; q++) {
        int f = t + 256 * q;
        int row = f >> 4, c8 = (f & 15) * 8;
        *(uint4*)(Ehp + (size_t)(i0 + row) * SEQ + j0 + c8) =
            *(const uint4*)(Est + row * 136 + c8);
    }
}

// ---- col pass over fp16 E ---------------------------------------------------
__global__ __launch_bounds__(256) void colpass_h(
    const __half* __restrict__ Eh, const float* __restrict__ rvec,
    float* __restrict__ colsum, int recip)
{
    const int bh = blockIdx.y;
    const int i0 = blockIdx.x * 64;
    const int t = threadIdx.x;
    __shared__ float rs[64];
    if (t < 64) {
        float rv = rvec[bh * SEQ + i0 + t];
        rs[t] = recip ? (MU_C / rv) : rv;
    }
    __syncthreads();

    const __half* Ep = Eh + (size_t)bh * SEQ * SEQ + (size_t)i0 * SEQ;
    const int j = t * 4;
    float ax = 0.f, ay = 0.f, az = 0.f, aw = 0.f;
#pragma unroll 8
    for (int i = 0; i < 64; i++) {
        uint2 raw = *(const uint2*)(Ep + (size_t)i * SEQ + j);
        float2 f0 = __half22float2(*(__half2*)&raw.x);
        float2 f1 = __half22float2(*(__half2*)&raw.y);
        float rv = rs[i];
        ax = fmaf(f0.x, rv, ax); ay = fmaf(f0.y, rv, ay);
        az = fmaf(f1.x, rv, az); aw = fmaf(f1.y, rv, aw);
    }
    atomicAdd(&colsum[bh * SEQ + j + 0], ax);
    atomicAdd(&colsum[bh * SEQ + j + 1], ay);
    atomicAdd(&colsum[bh * SEQ + j + 2], az);
    atomicAdd(&colsum[bh * SEQ + j + 3], aw);
}

// ---- fused row+col pass ------------------------------------------------------
__global__ __launch_bounds__(256) void rc_fused_h(
    const __half* __restrict__ Eh, const float* __restrict__ cs_in,
    float* __restrict__ cs_out, float* __restrict__ rvec)
{
    __shared__ float cs[SEQ];
    __shared__ float rl[32];
    const int bh = blockIdx.y, i0 = blockIdx.x * 32;
    const int t = threadIdx.x, lane = t & 31, w = t >> 5;

#pragma unroll
    for (int q = 0; q < 4; q++) {
        int j = t + 256 * q;
        cs[j] = NU_C / cs_in[bh * SEQ + j];
    }
    __syncthreads();

    const __half* Ep = Eh + (size_t)bh * SEQ * SEQ + (size_t)i0 * SEQ;

#pragma unroll
    for (int rr = 0; rr < 4; rr++) {
        const int row = w * 4 + rr;
        const __half* Er = Ep + (size_t)row * SEQ;
        float acc = 0.f;
#pragma unroll
        for (int it = 0; it < 4; it++) {
            int j = it * 256 + lane * 8;
            uint4 raw = *(const uint4*)(Er + j);
            const __half2* hp = (const __half2*)&raw;
#pragma unroll
            for (int p = 0; p < 4; p++) {
                float2 f = __half22float2(hp[p]);
                acc += f.x * cs[j + p * 2] + f.y * cs[j + p * 2 + 1];
            }
        }
#pragma unroll
        for (int o = 16; o > 0; o >>= 1)
            acc += __shfl_xor_sync(0xffffffffu, acc, o);
        if (lane == 0) {
            float rv = MU_C / acc;
            rl[row] = rv;
            rvec[bh * SEQ + i0 + row] = rv;
        }
    }
    __syncthreads();

    const int j = t * 4;
    float ax = 0.f, ay = 0.f, az = 0.f, aw = 0.f;
#pragma unroll 8
    for (int i = 0; i < 32; i++) {
        uint2 raw = *(const uint2*)(Ep + (size_t)i * SEQ + j);
        float2 f0 = __half22float2(*(__half2*)&raw.x);
        float2 f1 = __half22float2(*(__half2*)&raw.y);
        float rv = rl[i];
        ax = fmaf(f0.x, rv, ax); ay = fmaf(f0.y, rv, ay);
        az = fmaf(f1.x, rv, az); aw = fmaf(f1.y, rv, aw);
    }
    atomicAdd(&cs_out[bh * SEQ + j + 0], ax);
    atomicAdd(&cs_out[bh * SEQ + j + 1], ay);
    atomicAdd(&cs_out[bh * SEQ + j + 2], az);
    atomicAdd(&cs_out[bh * SEQ + j + 3], aw);
}

// --- per-head AV: fp16 mma, BK=64, register-prefetch pipeline, 1-buf smem ----
__global__ __launch_bounds__(256) void av_gemm(
    const __half* __restrict__ Eh, const float* __restrict__ r,
    const float* __restrict__ colsum3, const __half* __restrict__ qkv,
    float* __restrict__ attn, __half* __restrict__ ho, int write_attn)
{
    __shared__ __half Es[128 * 72];   // [i][j-chunk], 64 j + 8 pad
    __shared__ __half Vs[64 * 72];    // [j][d]
    __shared__ float cr[SEQ];
    __shared__ float rn[128];

    const int bh = blockIdx.y, b = bh >> 3, h = bh & 7;
    const int i0 = blockIdx.x * 128;
    const int t = threadIdx.x;
    const int lane = t & 31, w = t >> 5;
    const int wm = w & 3, wn = w >> 2;
    const int g = lane >> 2, tc = lane & 3;
    const int m0w = wm * 32, n0w = wn * 32;

    if (t < 128) rn[t] = r[bh * SEQ + i0 + t] * 1024.0f;
#pragma unroll
    for (int q = 0; q < 4; q++) {
        int j = t + 256 * q;
        cr[j] = NU_C / colsum3[bh * SEQ + j];
    }
    __syncthreads();

    const __half* Ep = Eh + (size_t)bh * SEQ * SEQ;
    const __half* vb = qkv + (size_t)b * SEQ * QKVW + 1024 + h * DHEAD;
    float* ap = attn + (size_t)bh * SEQ * SEQ;

    float4 acc[2][4];
#pragma unroll
    for (int mf = 0; mf < 2; mf++)
#pragma unroll
        for (int nf = 0; nf < 4; nf++) acc[mf][nf] = make_float4(0.f, 0.f, 0.f, 0.f);

    const u32 aAddrBase = sptr(Es) + ((lane & 15) * 72 + ((lane >> 4) << 3)) * 2;
    const u32 bAddrBase = sptr(Vs) +
        ((((lane >> 3) & 1) * 8 + (lane & 7)) * 72 + ((lane >> 4) << 3)) * 2;

    // per-thread load coords
    const int ei = t >> 3, ec8 = (t & 7) * 8;          // E: rows ei+32q
    const int vrw = t >> 3, vc8 = (t & 7) * 8;         // V: rows vrw+32q

    uint4 er[4], vr[2];
    // prologue: load tile 0 into regs
#pragma unroll
    for (int q = 0; q < 4; q++)
        er[q] = *(const uint4*)(Ep + (size_t)(i0 + ei + 32 * q) * SEQ + ec8);
#pragma unroll
    for (int q = 0; q < 2; q++)
        vr[q] = *(const uint4*)(vb + (size_t)(vrw + 32 * q) * QKVW + vc8);

    for (int jt = 0; jt < 16; jt++) {
        const int j0 = jt * 64;
        // store regs (tile jt) to smem + fused attn write
#pragma unroll
        for (int q = 0; q < 4; q++) {
            int i = ei + 32 * q;
            *(uint4*)(Es + i * 72 + ec8) = er[q];
            if (write_attn) {
                float rv = rn[i];
                const __half2* hp = (const __half2*)&er[q];
                float* dst = ap + (size_t)(i0 + i) * SEQ + j0 + ec8;
#pragma unroll
                for (int p = 0; p < 4; p++) {
                    float2 e = __half22float2(hp[p]);
                    float2 o;
                    o.x = rv * e.x * cr[j0 + ec8 + p * 2];
                    o.y = rv * e.y * cr[j0 + ec8 + p * 2 + 1];
                    *(float2*)(dst + p * 2) = o;
                }
            }
        }
#pragma unroll
        for (int q = 0; q < 2; q++) {
            int row = vrw + 32 * q;
            float cw = cr[j0 + row];
            const __half2* hp = (const __half2*)&vr[q];
            __half2* dst = (__half2*)(Vs + row * 72 + vc8);
#pragma unroll
            for (int p = 0; p < 4; p++) {
                float2 v = __half22float2(hp[p]);
                dst[p] = __floats2half2_rn(v.x * cw, v.y * cw);
            }
        }
        __syncthreads();

        // prefetch tile jt+1 into regs (overlaps with mma below)
        if (jt + 1 < 16) {
            const int j0n = (jt + 1) * 64;
#pragma unroll
            for (int q = 0; q < 4; q++)
                er[q] = *(const uint4*)(Ep + (size_t)(i0 + ei + 32 * q) * SEQ + j0n + ec8);
#pragma unroll
            for (int q = 0; q < 2; q++)
                vr[q] = *(const uint4*)(vb + (size_t)(j0n + vrw + 32 * q) * QKVW + vc8);
        }

        // compute on smem tile jt
#pragma unroll
        for (int ks = 0; ks < 64; ks += 16) {
            u32 a[2][4];
#pragma unroll
            for (int mf = 0; mf < 2; mf++)
                ldsm_x4(a[mf][0], a[mf][1], a[mf][2], a[mf][3],
                        aAddrBase + ((m0w + mf * 16) * 72 + ks) * 2);
#pragma unroll
            for (int nb = 0; nb < 2; nb++) {
                u32 b0, b1, b2, b3;
                ldsm_x4t(b0, b1, b2, b3,
                         bAddrBase + (ks * 72 + n0w + nb * 16) * 2);
                mma_f16(acc[0][nb * 2 + 0], a[0], b0, b1);
                mma_f16(acc[0][nb * 2 + 1], a[0], b2, b3);
                mma_f16(acc[1][nb * 2 + 0], a[1], b0, b1);
                mma_f16(acc[1][nb * 2 + 1], a[1], b2, b3);
            }
        }
        __syncthreads();
    }
#pragma unroll
    for (int mf = 0; mf < 2; mf++) {
        int il = m0w + mf * 16 + g;
        float rv0 = rn[il], rv1 = rn[il + 8];
        __half* hp0 = ho + (size_t)(b * SEQ + i0 + il) * DIMV + h * DHEAD;
        __half* hp1 = ho + (size_t)(b * SEQ + i0 + il + 8) * DIMV + h * DHEAD;
#pragma unroll
        for (int nf = 0; nf < 4; nf++) {
            int gc = n0w + nf * 8 + tc * 2;
            *(__half2*)(hp0 + gc) =
                __floats2half2_rn(acc[mf][nf].x * rv0, acc[mf][nf].y * rv0);
            *(__half2*)(hp1 + gc) =
                __floats2half2_rn(acc[mf][nf].z * rv1, acc[mf][nf].w * rv1);
        }
    }
}

// ---------------- launcher ---------------------------------------------------
extern "C" void kernel_launch(void* const* d_in, const int* in_sizes, int n_in,
                              void* d_out, int out_size)
{
    const float* x    = (const float*)d_in[0];
    const float* Wqkv = (const float*)d_in[1];
    const float* Wout = (const float*)d_in[2];
    const float* bout = (const float*)d_in[3];
    float* out = (float*)d_out;

    float *rp, *rsp, *c1p, *c2p, *c3p;
    __half *xh, *wqh, *woh, *qkvp, *Ehp, *hop;
    cudaGetSymbolAddress((void**)&xh,   g_xh);
    cudaGetSymbolAddress((void**)&wqh,  g_wqh);
    cudaGetSymbolAddress((void**)&woh,  g_woh);
    cudaGetSymbolAddress((void**)&qkvp, g_qkv);
    cudaGetSymbolAddress((void**)&Ehp,  g_Eh);
    cudaGetSymbolAddress((void**)&rp,   g_r);
    cudaGetSymbolAddress((void**)&rsp,  g_rowsum);
    cudaGetSymbolAddress((void**)&c1p,  g_cs1);
    cudaGetSymbolAddress((void**)&c2p,  g_cs2);
    cudaGetSymbolAddress((void**)&c3p,  g_cs3);
    cudaGetSymbolAddress((void**)&hop,  g_ho);

    const size_t FIN = (size_t)BQ * SEQ * DIMV;
    const size_t ATT = (size_t)NHEADS * SEQ * SEQ;
    float* fin_ptr = 0;
    float* attn_ptr = 0;
    if ((size_t)out_size >= FIN + ATT) { fin_ptr = out; attn_ptr = out + FIN; }
    else if ((size_t)out_size == ATT)  { attn_ptr = out; }
    else                               { fin_ptr = out; }

    // 0) fp32 -> fp16 operand conversion + accumulator zeroing
    prep<<<592, 256>>>(x, Wqkv, Wout, xh, wqh, woh, rsp, c1p, c2p, c3p);

    // 1) qkv = x @ W_qkv  (pure fp16 mma, double-buffered)
    gemm_hh<1><<<dim3(QKVW / 128, (BQ * SEQ) / 128), 256>>>(
        xh, wqh, qkvp, BQ * SEQ, QKVW, DIMV, (const float*)0);

    // 2) E = exp(-scale*q k^T) fp16 (coalesced stores), fused rowsum
    qk_dots_exp<<<dim3(SEQ / 128, SEQ / 128, NHEADS), 256>>>(qkvp, Ehp, rsp);

    // 3) Sinkhorn: col1, then two fused (row+col) passes
    colpass_h<<<dim3(SEQ / 64, NHEADS), 256>>>(Ehp, rsp, c1p, 1);
    rc_fused_h<<<dim3(SEQ / 32, NHEADS), 256>>>(Ehp, c1p, c2p, rp);   // r2, cs2
    rc_fused_h<<<dim3(SEQ / 32, NHEADS), 256>>>(Ehp, c2p, c3p, rp);   // r3, cs3

    // 4) attn = r*E*c*n (fused fp32 write) and ho = attn @ V (reg-prefetch)
    av_gemm<<<dim3(SEQ / 128, NHEADS), 256>>>(
        Ehp, rp, c3p, qkvp, attn_ptr ? attn_ptr : (float*)out, hop,
        attn_ptr ? 1 : 0);

    // 5) final = ho @ W_out + b_out  (pure fp16 mma, double-buffered)
    if (fin_ptr)
        gemm_hh<0><<<dim3(DIMV / 128, (BQ * SEQ) / 128), 256>>>(
            hop, woh, fin_ptr, BQ * SEQ, DIMV, DIMV, bout);
}